// round 4
// baseline (speedup 1.0000x reference)
#include <cuda_runtime.h>
#include <math.h>
#include <stdint.h>

#define B_  32
#define N_  1024
#define C_  768
#define H_  12
#define D_  64
#define L_  128

// ---------------- scratch (device globals: no allocations allowed) ----------
__device__ float g_Q [B_*N_*C_];        // Q projection (B,N,C)
__device__ float g_xp[B_*L_*C_];        // pooled first-128 tokens
__device__ float g_KV[B_*L_*2*C_];      // K|V projections of pooled tokens
__device__ float g_kf[B_*H_*L_*D_];     // k_full (B,H,128,64)
__device__ float g_vf[B_*H_*L_*D_];     // v_full
__device__ float g_ao[B_*N_*C_];        // attention output (B,N,C)

__device__ __forceinline__ unsigned f2tf(float f) {
    unsigned u;
    asm("cvt.rna.tf32.f32 %0, %1;" : "=r"(u) : "f"(f));
    return u;
}

__device__ __forceinline__ void mma_tf32(
    float* c, uint32_t a0, uint32_t a1, uint32_t a2, uint32_t a3,
    uint32_t b0, uint32_t b1)
{
    asm volatile(
        "mma.sync.aligned.m16n8k8.row.col.f32.tf32.tf32.f32 "
        "{%0,%1,%2,%3}, {%4,%5,%6,%7}, {%8,%9}, {%0,%1,%2,%3};"
        : "+f"(c[0]), "+f"(c[1]), "+f"(c[2]), "+f"(c[3])
        : "r"(a0), "r"(a1), "r"(a2), "r"(a3), "r"(b0), "r"(b1));
}

// ---------------- pooling: xp[b,p,c] = 0.5*(x[b,2p,c]+x[b,2p+1,c]) ----------
__global__ void pool_kernel(const float* __restrict__ x, float* __restrict__ xp)
{
    int i = blockIdx.x * blockDim.x + threadIdx.x;      // float4 index
    const int TOT4 = B_*L_*C_/4;
    if (i >= TOT4) return;
    int c4 = i % (C_/4);
    int p  = (i / (C_/4)) % L_;
    int b  = i / (C_/4 * L_);
    long base = (long)b*N_*C_ + (long)(2*p)*C_ + c4*4;
    float4 a = *reinterpret_cast<const float4*>(x + base);
    float4 c = *reinterpret_cast<const float4*>(x + base + C_);
    float4 o;
    o.x = 0.5f*(a.x+c.x); o.y = 0.5f*(a.y+c.y);
    o.z = 0.5f*(a.z+c.z); o.w = 0.5f*(a.w+c.w);
    *reinterpret_cast<float4*>(xp + (long)i*4) = o;
}

// -------- tf32 tensor-core GEMM, double-buffered: C = A*B + bias ------------
// 128x128 tile, BK=32, 256 threads (8 warps), warp tile 64x32.
#define AS_W (128*36)
#define BS_W (32*132)
#define GEMM_SMEM ((AS_W + BS_W) * 2 * 4)

__global__ __launch_bounds__(256) void sgemm_tf32(
    const float* __restrict__ A, const float* __restrict__ Bm,
    const float* __restrict__ bias, float* __restrict__ C,
    int K, int lda, int ldb, int ldc)
{
    extern __shared__ uint32_t smu[];
    // As[buf][m][36], Bs[buf][k][132]
    uint32_t* AsBase = smu;
    uint32_t* BsBase = smu + 2*AS_W;

    const int t    = threadIdx.x;
    const int warp = t >> 5;
    const int lane = t & 31;
    const int group = lane >> 2;
    const int tid4  = lane & 3;
    const int wm = (warp & 1) * 64;
    const int wn = (warp >> 1) * 32;

    const int bm = blockIdx.y * 128, bn = blockIdx.x * 128;

    const int am  = t >> 3;            // 0..31 (+i*32)
    const int ak4 = (t & 7) * 4;       // 0,4,..28
    const int bk  = t >> 5;            // 0..7 (+i*8)
    const int bn4 = (t & 31) * 4;      // 0..124

    float acc[4][4][4];
    #pragma unroll
    for (int mf = 0; mf < 4; mf++)
        #pragma unroll
        for (int nf = 0; nf < 4; nf++)
            #pragma unroll
            for (int r = 0; r < 4; r++) acc[mf][nf][r] = 0.f;

    float4 pa[4], pb[4];

    // prologue: load tile 0 into regs, store to buffer 0
    #pragma unroll
    for (int i = 0; i < 4; i++)
        pa[i] = *reinterpret_cast<const float4*>(
            A + (long)(bm + am + i*32)*lda + ak4);
    #pragma unroll
    for (int i = 0; i < 4; i++)
        pb[i] = *reinterpret_cast<const float4*>(
            Bm + (long)(bk + i*8)*ldb + bn + bn4);

    {
        uint32_t* As0 = AsBase;
        uint32_t* Bs0 = BsBase;
        #pragma unroll
        for (int i = 0; i < 4; i++) {
            uint32_t* d = &As0[(am + i*32)*36 + ak4];
            d[0]=f2tf(pa[i].x); d[1]=f2tf(pa[i].y);
            d[2]=f2tf(pa[i].z); d[3]=f2tf(pa[i].w);
        }
        #pragma unroll
        for (int i = 0; i < 4; i++) {
            uint32_t* d = &Bs0[(bk + i*8)*132 + bn4];
            d[0]=f2tf(pb[i].x); d[1]=f2tf(pb[i].y);
            d[2]=f2tf(pb[i].z); d[3]=f2tf(pb[i].w);
        }
    }
    __syncthreads();

    for (int k0 = 0; k0 < K; k0 += 32) {
        const int buf = (k0 >> 5) & 1;
        const bool has_next = (k0 + 32) < K;
        uint32_t* As = AsBase + buf*AS_W;
        uint32_t* Bs = BsBase + buf*BS_W;

        // issue next tile's LDGs early — hidden by compute
        if (has_next) {
            #pragma unroll
            for (int i = 0; i < 4; i++)
                pa[i] = *reinterpret_cast<const float4*>(
                    A + (long)(bm + am + i*32)*lda + k0 + 32 + ak4);
            #pragma unroll
            for (int i = 0; i < 4; i++)
                pb[i] = *reinterpret_cast<const float4*>(
                    Bm + (long)(k0 + 32 + bk + i*8)*ldb + bn + bn4);
        }

        #pragma unroll
        for (int ks = 0; ks < 4; ks++) {
            const int kk = ks * 8;
            uint32_t a[4][4], b[4][2];
            #pragma unroll
            for (int mf = 0; mf < 4; mf++) {
                int r0 = wm + mf*16 + group;
                a[mf][0] = As[(r0    )*36 + kk + tid4];
                a[mf][1] = As[(r0 + 8)*36 + kk + tid4];
                a[mf][2] = As[(r0    )*36 + kk + tid4 + 4];
                a[mf][3] = As[(r0 + 8)*36 + kk + tid4 + 4];
            }
            #pragma unroll
            for (int nf = 0; nf < 4; nf++) {
                int cc = wn + nf*8 + group;
                b[nf][0] = Bs[(kk + tid4    )*132 + cc];
                b[nf][1] = Bs[(kk + tid4 + 4)*132 + cc];
            }
            #pragma unroll
            for (int mf = 0; mf < 4; mf++)
                #pragma unroll
                for (int nf = 0; nf < 4; nf++)
                    mma_tf32(acc[mf][nf], a[mf][0], a[mf][1], a[mf][2], a[mf][3],
                             b[nf][0], b[nf][1]);
        }

        // store prefetched tile into alternate buffer
        if (has_next) {
            uint32_t* Asn = AsBase + (buf^1)*AS_W;
            uint32_t* Bsn = BsBase + (buf^1)*BS_W;
            #pragma unroll
            for (int i = 0; i < 4; i++) {
                uint32_t* d = &Asn[(am + i*32)*36 + ak4];
                d[0]=f2tf(pa[i].x); d[1]=f2tf(pa[i].y);
                d[2]=f2tf(pa[i].z); d[3]=f2tf(pa[i].w);
            }
            #pragma unroll
            for (int i = 0; i < 4; i++) {
                uint32_t* d = &Bsn[(bk + i*8)*132 + bn4];
                d[0]=f2tf(pb[i].x); d[1]=f2tf(pb[i].y);
                d[2]=f2tf(pb[i].z); d[3]=f2tf(pb[i].w);
            }
        }
        __syncthreads();
    }

    #pragma unroll
    for (int mf = 0; mf < 4; mf++) {
        int r0 = bm + wm + mf*16 + group;
        #pragma unroll
        for (int nf = 0; nf < 4; nf++) {
            int c0 = bn + wn + nf*8 + tid4*2;
            float2 bi = *reinterpret_cast<const float2*>(bias + c0);
            float2 o0, o1;
            o0.x = acc[mf][nf][0] + bi.x; o0.y = acc[mf][nf][1] + bi.y;
            o1.x = acc[mf][nf][2] + bi.x; o1.y = acc[mf][nf][3] + bi.y;
            *reinterpret_cast<float2*>(C + (long)r0*ldc + c0) = o0;
            *reinterpret_cast<float2*>(C + (long)(r0+8)*ldc + c0) = o1;
        }
    }
}

// ------------- kc/vc = E^T @ {K,V}_head, then append bank rows --------------
__global__ __launch_bounds__(256) void kvcompress(
    const float* __restrict__ KV, const float* __restrict__ E_k,
    const float* __restrict__ E_v, const float* __restrict__ k_bank,
    const float* __restrict__ v_bank, float* __restrict__ kf,
    float* __restrict__ vf)
{
    int which = blockIdx.x;      // 0: K, 1: V
    int h = blockIdx.y, b = blockIdx.z;
    const float* E    = which ? E_v : E_k;
    const float* bank = which ? v_bank : k_bank;
    float* out = (which ? vf : kf) + ((long)(b*H_ + h) * L_) * D_;

    __shared__ float Es[64][64];
    __shared__ float Ks[64][64];

    int tid = threadIdx.x;
    int d  = tid & 63;
    int cg = tid >> 6;
    float acc[16];
    #pragma unroll
    for (int i = 0; i < 16; i++) acc[i] = 0.f;

    for (int s0 = 0; s0 < L_; s0 += 64) {
        for (int i = tid*4; i < 64*64; i += 1024)
            *reinterpret_cast<float4*>(&Es[i>>6][i&63]) =
                *reinterpret_cast<const float4*>(E + (long)(s0 + (i>>6))*64 + (i&63));
        for (int i = tid; i < 64*16; i += 256) {
            int r = i >> 4, c4 = (i & 15)*4;
            *reinterpret_cast<float4*>(&Ks[r][c4]) =
                *reinterpret_cast<const float4*>(
                    KV + (long)b*L_*2*C_ + (long)(s0+r)*2*C_ + which*C_ + h*D_ + c4);
        }
        __syncthreads();
        for (int s = 0; s < 64; s++) {
            float kv = Ks[s][d];
            #pragma unroll
            for (int i = 0; i < 16; i++)
                acc[i] += Es[s][cg*16 + i] * kv;
        }
        __syncthreads();
    }
    #pragma unroll
    for (int i = 0; i < 16; i++)
        out[(long)(cg*16 + i)*D_ + d] = acc[i];

    for (int i = tid; i < 64*64; i += 256) {
        int r = i >> 6, dd = i & 63;
        out[(long)(64 + r)*D_ + dd] = bank[(long)b*64*C_ + (long)r*C_ + h*D_ + dd];
    }
}

// -------- tensor-core attention: 128 queries/block, 128 keys, tf32 ----------
#define KS_STRIDE 68
#define VT_STRIDE 132
#define PS_STRIDE 132
#define ATTN_SMEM ((128*68 + 64*132 + 128*132 + 128*68) * 4)

__global__ __launch_bounds__(256) void attn_tc(
    const float* __restrict__ Q, const float* __restrict__ kf,
    const float* __restrict__ vf, float* __restrict__ O)
{
    extern __shared__ uint32_t smu[];
    uint32_t* Ks = smu;                       // [128][68]
    uint32_t* Vt = Ks + 128*KS_STRIDE;        // [64][132]
    uint32_t* Ps = Vt + 64*VT_STRIDE;         // [128][132]
    uint32_t* Qs = Ps + 128*PS_STRIDE;        // [128][68]

    const int t = threadIdx.x;
    const int warp = t >> 5, lane = t & 31;
    const int group = lane >> 2, tid4 = lane & 3;
    const int qb = blockIdx.x, h = blockIdx.y, b = blockIdx.z;

    const float* kfp = kf + (long)(b*H_ + h) * L_ * D_;
    const float* vfp = vf + (long)(b*H_ + h) * L_ * D_;

    for (int i = t*4; i < L_*D_; i += 1024) {
        float4 v = *reinterpret_cast<const float4*>(kfp + i);
        int k = i >> 6, d = i & 63;
        uint32_t* dst = &Ks[k*KS_STRIDE + d];
        dst[0]=f2tf(v.x); dst[1]=f2tf(v.y); dst[2]=f2tf(v.z); dst[3]=f2tf(v.w);
    }
    {
        int k = t & 127;
        int d0 = (t >> 7) * 32;
        #pragma unroll
        for (int d = 0; d < 32; d += 4) {
            float4 v = *reinterpret_cast<const float4*>(vfp + k*64 + d0 + d);
            Vt[(d0+d+0)*VT_STRIDE + k] = f2tf(v.x);
            Vt[(d0+d+1)*VT_STRIDE + k] = f2tf(v.y);
            Vt[(d0+d+2)*VT_STRIDE + k] = f2tf(v.z);
            Vt[(d0+d+3)*VT_STRIDE + k] = f2tf(v.w);
        }
    }
    {
        long base = ((long)b*N_ + qb*128) * C_ + h*D_;
        for (int i = t*4; i < 128*64; i += 1024) {
            int q = i >> 6, d = i & 63;
            float4 v = *reinterpret_cast<const float4*>(Q + base + (long)q*C_ + d);
            uint32_t* dst = &Qs[q*KS_STRIDE + d];
            dst[0]=f2tf(v.x); dst[1]=f2tf(v.y); dst[2]=f2tf(v.z); dst[3]=f2tf(v.w);
        }
    }
    __syncthreads();

    float accS[16][4];
    #pragma unroll
    for (int nt = 0; nt < 16; nt++)
        #pragma unroll
        for (int r = 0; r < 4; r++) accS[nt][r] = 0.f;

    const int qrow = warp*16;
    #pragma unroll
    for (int kf8 = 0; kf8 < 8; kf8++) {
        const int kk = kf8*8;
        uint32_t a0 = Qs[(qrow+group  )*KS_STRIDE + kk + tid4];
        uint32_t a1 = Qs[(qrow+group+8)*KS_STRIDE + kk + tid4];
        uint32_t a2 = Qs[(qrow+group  )*KS_STRIDE + kk + tid4 + 4];
        uint32_t a3 = Qs[(qrow+group+8)*KS_STRIDE + kk + tid4 + 4];
        #pragma unroll
        for (int nt = 0; nt < 16; nt++) {
            uint32_t b0 = Ks[(nt*8+group)*KS_STRIDE + kk + tid4];
            uint32_t b1 = Ks[(nt*8+group)*KS_STRIDE + kk + tid4 + 4];
            mma_tf32(accS[nt], a0, a1, a2, a3, b0, b1);
        }
    }

    const float scale = 0.125f;
    float m0 = -1e30f, m1 = -1e30f;
    #pragma unroll
    for (int nt = 0; nt < 16; nt++) {
        accS[nt][0] *= scale; accS[nt][1] *= scale;
        accS[nt][2] *= scale; accS[nt][3] *= scale;
        m0 = fmaxf(m0, fmaxf(accS[nt][0], accS[nt][1]));
        m1 = fmaxf(m1, fmaxf(accS[nt][2], accS[nt][3]));
    }
    m0 = fmaxf(m0, __shfl_xor_sync(0xffffffff, m0, 1));
    m0 = fmaxf(m0, __shfl_xor_sync(0xffffffff, m0, 2));
    m1 = fmaxf(m1, __shfl_xor_sync(0xffffffff, m1, 1));
    m1 = fmaxf(m1, __shfl_xor_sync(0xffffffff, m1, 2));

    float l0 = 0.f, l1 = 0.f;
    #pragma unroll
    for (int nt = 0; nt < 16; nt++) {
        accS[nt][0] = expf(accS[nt][0] - m0);
        accS[nt][1] = expf(accS[nt][1] - m0);
        accS[nt][2] = expf(accS[nt][2] - m1);
        accS[nt][3] = expf(accS[nt][3] - m1);
        l0 += accS[nt][0] + accS[nt][1];
        l1 += accS[nt][2] + accS[nt][3];
    }
    l0 += __shfl_xor_sync(0xffffffff, l0, 1);
    l0 += __shfl_xor_sync(0xffffffff, l0, 2);
    l1 += __shfl_xor_sync(0xffffffff, l1, 1);
    l1 += __shfl_xor_sync(0xffffffff, l1, 2);
    float rl0 = 1.f / l0, rl1 = 1.f / l1;

    #pragma unroll
    for (int nt = 0; nt < 16; nt++) {
        int col = nt*8 + tid4*2;
        uint2 p0, p1;
        p0.x = f2tf(accS[nt][0]*rl0); p0.y = f2tf(accS[nt][1]*rl0);
        p1.x = f2tf(accS[nt][2]*rl1); p1.y = f2tf(accS[nt][3]*rl1);
        *reinterpret_cast<uint2*>(&Ps[(qrow+group  )*PS_STRIDE + col]) = p0;
        *reinterpret_cast<uint2*>(&Ps[(qrow+group+8)*PS_STRIDE + col]) = p1;
    }
    __syncwarp();

    float accO[8][4];
    #pragma unroll
    for (int nt = 0; nt < 8; nt++)
        #pragma unroll
        for (int r = 0; r < 4; r++) accO[nt][r] = 0.f;

    #pragma unroll
    for (int kf8 = 0; kf8 < 16; kf8++) {
        const int kk = kf8*8;
        uint32_t a0 = Ps[(qrow+group  )*PS_STRIDE + kk + tid4];
        uint32_t a1 = Ps[(qrow+group+8)*PS_STRIDE + kk + tid4];
        uint32_t a2 = Ps[(qrow+group  )*PS_STRIDE + kk + tid4 + 4];
        uint32_t a3 = Ps[(qrow+group+8)*PS_STRIDE + kk + tid4 + 4];
        #pragma unroll
        for (int nt = 0; nt < 8; nt++) {
            uint32_t b0 = Vt[(nt*8+group)*VT_STRIDE + kk + tid4];
            uint32_t b1 = Vt[(nt*8+group)*VT_STRIDE + kk + tid4 + 4];
            mma_tf32(accO[nt], a0, a1, a2, a3, b0, b1);
        }
    }

    long row0 = (long)b*N_ + qb*128 + qrow + group;
    #pragma unroll
    for (int nt = 0; nt < 8; nt++) {
        int col = h*D_ + nt*8 + tid4*2;
        float2 o0, o1;
        o0.x = accO[nt][0]; o0.y = accO[nt][1];
        o1.x = accO[nt][2]; o1.y = accO[nt][3];
        *reinterpret_cast<float2*>(O + row0*C_ + col) = o0;
        *reinterpret_cast<float2*>(O + (row0+8)*C_ + col) = o1;
    }
}

// ---------------------------------------------------------------------------
extern "C" void kernel_launch(void* const* d_in, const int* in_sizes, int n_in,
                              void* d_out, int out_size)
{
    const float* x      = (const float*)d_in[0];
    const float* Wqkv   = (const float*)d_in[1];
    const float* bqkv   = (const float*)d_in[2];
    const float* E_k    = (const float*)d_in[3];
    const float* E_v    = (const float*)d_in[4];
    const float* Wproj  = (const float*)d_in[5];
    const float* bproj  = (const float*)d_in[6];
    const float* k_bank = (const float*)d_in[7];
    const float* v_bank = (const float*)d_in[8];

    float *Q, *xp, *KV, *kf, *vf, *ao;
    cudaGetSymbolAddress((void**)&Q,  g_Q);
    cudaGetSymbolAddress((void**)&xp, g_xp);
    cudaGetSymbolAddress((void**)&KV, g_KV);
    cudaGetSymbolAddress((void**)&kf, g_kf);
    cudaGetSymbolAddress((void**)&vf, g_vf);
    cudaGetSymbolAddress((void**)&ao, g_ao);

    cudaFuncSetAttribute(sgemm_tf32,
                         cudaFuncAttributeMaxDynamicSharedMemorySize, GEMM_SMEM);
    cudaFuncSetAttribute(attn_tc,
                         cudaFuncAttributeMaxDynamicSharedMemorySize, ATTN_SMEM);

    // 1) pooled tokens (first 128 only are ever used)
    pool_kernel<<<(B_*L_*C_/4 + 255)/256, 256>>>(x, xp);

    // 2) Q = x @ Wqkv[:,0:768] + bqkv[0:768]
    sgemm_tf32<<<dim3(C_/128, B_*N_/128), 256, GEMM_SMEM>>>(
        x, Wqkv, bqkv, Q, C_, C_, 3*C_, C_);

    // 3) KV = xp @ Wqkv[:,768:2304] + bqkv[768:]
    sgemm_tf32<<<dim3(2*C_/128, B_*L_/128), 256, GEMM_SMEM>>>(
        xp, Wqkv + C_, bqkv + C_, KV, C_, C_, 3*C_, 2*C_);

    // 4) compress + bank concat
    kvcompress<<<dim3(2, H_, B_), 256>>>(KV, E_k, E_v, k_bank, v_bank, kf, vf);

    // 5) tensor-core attention
    attn_tc<<<dim3(N_/128, H_, B_), 256, ATTN_SMEM>>>(Q, kf, vf, ao);

    // 6) out = ao @ Wproj + bproj
    sgemm_tf32<<<dim3(C_/128, B_*N_/128), 256, GEMM_SMEM>>>(
        ao, Wproj, bproj, (float*)d_out, C_, C_, C_, C_);
}

// round 5
// speedup vs baseline: 1.4087x; 1.4087x over previous
#include <cuda_runtime.h>
#include <cuda_fp16.h>
#include <math.h>
#include <stdint.h>

#define B_  32
#define N_  1024
#define C_  768
#define H_  12
#define D_  64
#define L_  128

// ---------------- scratch (device globals: no allocations allowed) ----------
__device__ float g_Q [B_*N_*C_];        // Q projection (B,N,C)
__device__ float g_xp[B_*L_*C_];        // pooled first-128 tokens
__device__ float g_KV[B_*L_*2*C_];      // K|V projections of pooled tokens
__device__ float g_kf[B_*H_*L_*D_];     // k_full (B,H,128,64)
__device__ float g_vf[B_*H_*L_*D_];     // v_full
__device__ float g_ao[B_*N_*C_];        // attention output (B,N,C)

__device__ __forceinline__ unsigned f2tf(float f) {
    unsigned u;
    asm("cvt.rna.tf32.f32 %0, %1;" : "=r"(u) : "f"(f));
    return u;
}

__device__ __forceinline__ void mma_tf32(
    float* c, uint32_t a0, uint32_t a1, uint32_t a2, uint32_t a3,
    uint32_t b0, uint32_t b1)
{
    asm volatile(
        "mma.sync.aligned.m16n8k8.row.col.f32.tf32.tf32.f32 "
        "{%0,%1,%2,%3}, {%4,%5,%6,%7}, {%8,%9}, {%0,%1,%2,%3};"
        : "+f"(c[0]), "+f"(c[1]), "+f"(c[2]), "+f"(c[3])
        : "r"(a0), "r"(a1), "r"(a2), "r"(a3), "r"(b0), "r"(b1));
}

__device__ __forceinline__ void mma_f16(
    float* c, uint32_t a0, uint32_t a1, uint32_t a2, uint32_t a3,
    uint32_t b0, uint32_t b1)
{
    asm volatile(
        "mma.sync.aligned.m16n8k16.row.col.f32.f16.f16.f32 "
        "{%0,%1,%2,%3}, {%4,%5,%6,%7}, {%8,%9}, {%0,%1,%2,%3};"
        : "+f"(c[0]), "+f"(c[1]), "+f"(c[2]), "+f"(c[3])
        : "r"(a0), "r"(a1), "r"(a2), "r"(a3), "r"(b0), "r"(b1));
}

// ---------------- pooling: xp[b,p,c] = 0.5*(x[b,2p,c]+x[b,2p+1,c]) ----------
__global__ void pool_kernel(const float* __restrict__ x, float* __restrict__ xp)
{
    int i = blockIdx.x * blockDim.x + threadIdx.x;      // float4 index
    const int TOT4 = B_*L_*C_/4;
    if (i >= TOT4) return;
    int c4 = i % (C_/4);
    int p  = (i / (C_/4)) % L_;
    int b  = i / (C_/4 * L_);
    long base = (long)b*N_*C_ + (long)(2*p)*C_ + c4*4;
    float4 a = *reinterpret_cast<const float4*>(x + base);
    float4 c = *reinterpret_cast<const float4*>(x + base + C_);
    float4 o;
    o.x = 0.5f*(a.x+c.x); o.y = 0.5f*(a.y+c.y);
    o.z = 0.5f*(a.z+c.z); o.w = 0.5f*(a.w+c.w);
    *reinterpret_cast<float4*>(xp + (long)i*4) = o;
}

// -------- fp16 tensor-core GEMM, double-buffered: C = A*B + bias ------------
// 128x128 tile, BK=32, 256 threads (8 warps), warp tile 64x32.
// As: half2-words [128][20] (16 data words + 4 pad), Bs: half [32][136].
#define AW_STR 20
#define BH_STR 136
#define AS_WORDS (128*AW_STR)
#define BS_HALFS (32*BH_STR)

__global__ __launch_bounds__(256, 2) void hgemm(
    const float* __restrict__ A, const float* __restrict__ Bm,
    const float* __restrict__ bias, float* __restrict__ C,
    int K, int lda, int ldb, int ldc)
{
    __shared__ uint32_t Aw[2][AS_WORDS];
    __shared__ __half   Bh[2][BS_HALFS];

    const int t    = threadIdx.x;
    const int warp = t >> 5;
    const int lane = t & 31;
    const int group = lane >> 2;
    const int tid4  = lane & 3;
    const int wm = (warp & 1) * 64;
    const int wn = (warp >> 1) * 32;

    const int bm = blockIdx.y * 128, bn = blockIdx.x * 128;

    const int am  = t >> 3;            // 0..31 (+i*32)
    const int ak4 = (t & 7) * 4;       // 0,4,..28
    const int bk  = t >> 5;            // 0..7 (+i*8)
    const int bn4 = (t & 31) * 4;      // 0..124

    float acc[4][4][4];
    #pragma unroll
    for (int mf = 0; mf < 4; mf++)
        #pragma unroll
        for (int nf = 0; nf < 4; nf++)
            #pragma unroll
            for (int r = 0; r < 4; r++) acc[mf][nf][r] = 0.f;

    float4 pa[4], pb[4];

    // prologue: load slab 0
    #pragma unroll
    for (int i = 0; i < 4; i++)
        pa[i] = *reinterpret_cast<const float4*>(
            A + (long)(bm + am + i*32)*lda + ak4);
    #pragma unroll
    for (int i = 0; i < 4; i++)
        pb[i] = *reinterpret_cast<const float4*>(
            Bm + (long)(bk + i*8)*ldb + bn + bn4);

    // store slab 0 into buffer 0
    #pragma unroll
    for (int i = 0; i < 4; i++) {
        __half2 h0 = __float22half2_rn(make_float2(pa[i].x, pa[i].y));
        __half2 h1 = __float22half2_rn(make_float2(pa[i].z, pa[i].w));
        uint32_t* d = &Aw[0][(am + i*32)*AW_STR + (ak4>>1)];
        d[0] = *reinterpret_cast<uint32_t*>(&h0);
        d[1] = *reinterpret_cast<uint32_t*>(&h1);
    }
    #pragma unroll
    for (int i = 0; i < 4; i++) {
        __half2 h0 = __float22half2_rn(make_float2(pb[i].x, pb[i].y));
        __half2 h1 = __float22half2_rn(make_float2(pb[i].z, pb[i].w));
        uint32_t* d = reinterpret_cast<uint32_t*>(&Bh[0][(bk + i*8)*BH_STR + bn4]);
        d[0] = *reinterpret_cast<uint32_t*>(&h0);
        d[1] = *reinterpret_cast<uint32_t*>(&h1);
    }
    __syncthreads();

    for (int k0 = 0; k0 < K; k0 += 32) {
        const int buf = (k0 >> 5) & 1;
        const bool has_next = (k0 + 32) < K;

        if (has_next) {
            #pragma unroll
            for (int i = 0; i < 4; i++)
                pa[i] = *reinterpret_cast<const float4*>(
                    A + (long)(bm + am + i*32)*lda + k0 + 32 + ak4);
            #pragma unroll
            for (int i = 0; i < 4; i++)
                pb[i] = *reinterpret_cast<const float4*>(
                    Bm + (long)(k0 + 32 + bk + i*8)*ldb + bn + bn4);
        }

        const uint32_t* Awb = Aw[buf];
        const __half*   Bhb = Bh[buf];

        #pragma unroll
        for (int ks = 0; ks < 2; ks++) {      // two k16 chunks
            const int kw = ks * 8;            // word offset in A row
            const int kb = ks * 16;           // half row offset in B
            uint32_t a[4][4], b[4][2];
            #pragma unroll
            for (int mf = 0; mf < 4; mf++) {
                int r0 = wm + mf*16 + group;
                a[mf][0] = Awb[(r0    )*AW_STR + kw + tid4];
                a[mf][1] = Awb[(r0 + 8)*AW_STR + kw + tid4];
                a[mf][2] = Awb[(r0    )*AW_STR + kw + tid4 + 4];
                a[mf][3] = Awb[(r0 + 8)*AW_STR + kw + tid4 + 4];
            }
            #pragma unroll
            for (int nf = 0; nf < 4; nf++) {
                int cc = wn + nf*8 + group;
                __half2 b0 = __halves2half2(
                    Bhb[(kb + 2*tid4    )*BH_STR + cc],
                    Bhb[(kb + 2*tid4 + 1)*BH_STR + cc]);
                __half2 b1 = __halves2half2(
                    Bhb[(kb + 2*tid4 + 8)*BH_STR + cc],
                    Bhb[(kb + 2*tid4 + 9)*BH_STR + cc]);
                b[nf][0] = *reinterpret_cast<uint32_t*>(&b0);
                b[nf][1] = *reinterpret_cast<uint32_t*>(&b1);
            }
            #pragma unroll
            for (int mf = 0; mf < 4; mf++)
                #pragma unroll
                for (int nf = 0; nf < 4; nf++)
                    mma_f16(acc[mf][nf], a[mf][0], a[mf][1], a[mf][2], a[mf][3],
                            b[nf][0], b[nf][1]);
        }

        if (has_next) {
            const int nb = buf ^ 1;
            #pragma unroll
            for (int i = 0; i < 4; i++) {
                __half2 h0 = __float22half2_rn(make_float2(pa[i].x, pa[i].y));
                __half2 h1 = __float22half2_rn(make_float2(pa[i].z, pa[i].w));
                uint32_t* d = &Aw[nb][(am + i*32)*AW_STR + (ak4>>1)];
                d[0] = *reinterpret_cast<uint32_t*>(&h0);
                d[1] = *reinterpret_cast<uint32_t*>(&h1);
            }
            #pragma unroll
            for (int i = 0; i < 4; i++) {
                __half2 h0 = __float22half2_rn(make_float2(pb[i].x, pb[i].y));
                __half2 h1 = __float22half2_rn(make_float2(pb[i].z, pb[i].w));
                uint32_t* d = reinterpret_cast<uint32_t*>(
                    &Bh[nb][(bk + i*8)*BH_STR + bn4]);
                d[0] = *reinterpret_cast<uint32_t*>(&h0);
                d[1] = *reinterpret_cast<uint32_t*>(&h1);
            }
        }
        __syncthreads();
    }

    #pragma unroll
    for (int mf = 0; mf < 4; mf++) {
        int r0 = bm + wm + mf*16 + group;
        #pragma unroll
        for (int nf = 0; nf < 4; nf++) {
            int c0 = bn + wn + nf*8 + tid4*2;
            float2 bi = *reinterpret_cast<const float2*>(bias + c0);
            float2 o0, o1;
            o0.x = acc[mf][nf][0] + bi.x; o0.y = acc[mf][nf][1] + bi.y;
            o1.x = acc[mf][nf][2] + bi.x; o1.y = acc[mf][nf][3] + bi.y;
            *reinterpret_cast<float2*>(C + (long)r0*ldc + c0) = o0;
            *reinterpret_cast<float2*>(C + (long)(r0+8)*ldc + c0) = o1;
        }
    }
}

// ------------- kc/vc = E^T @ {K,V}_head, then append bank rows --------------
__global__ __launch_bounds__(256) void kvcompress(
    const float* __restrict__ KV, const float* __restrict__ E_k,
    const float* __restrict__ E_v, const float* __restrict__ k_bank,
    const float* __restrict__ v_bank, float* __restrict__ kf,
    float* __restrict__ vf)
{
    int which = blockIdx.x;      // 0: K, 1: V
    int h = blockIdx.y, b = blockIdx.z;
    const float* E    = which ? E_v : E_k;
    const float* bank = which ? v_bank : k_bank;
    float* out = (which ? vf : kf) + ((long)(b*H_ + h) * L_) * D_;

    __shared__ float Es[64][64];
    __shared__ float Ks[64][64];

    int tid = threadIdx.x;
    int d  = tid & 63;
    int cg = tid >> 6;
    float acc[16];
    #pragma unroll
    for (int i = 0; i < 16; i++) acc[i] = 0.f;

    for (int s0 = 0; s0 < L_; s0 += 64) {
        for (int i = tid*4; i < 64*64; i += 1024)
            *reinterpret_cast<float4*>(&Es[i>>6][i&63]) =
                *reinterpret_cast<const float4*>(E + (long)(s0 + (i>>6))*64 + (i&63));
        for (int i = tid; i < 64*16; i += 256) {
            int r = i >> 4, c4 = (i & 15)*4;
            *reinterpret_cast<float4*>(&Ks[r][c4]) =
                *reinterpret_cast<const float4*>(
                    KV + (long)b*L_*2*C_ + (long)(s0+r)*2*C_ + which*C_ + h*D_ + c4);
        }
        __syncthreads();
        for (int s = 0; s < 64; s++) {
            float kv = Ks[s][d];
            #pragma unroll
            for (int i = 0; i < 16; i++)
                acc[i] += Es[s][cg*16 + i] * kv;
        }
        __syncthreads();
    }
    #pragma unroll
    for (int i = 0; i < 16; i++)
        out[(long)(cg*16 + i)*D_ + d] = acc[i];

    for (int i = tid; i < 64*64; i += 256) {
        int r = i >> 6, dd = i & 63;
        out[(long)(64 + r)*D_ + dd] = bank[(long)b*64*C_ + (long)r*C_ + h*D_ + dd];
    }
}

// -------- tensor-core attention: 128 queries/block, 128 keys, tf32 ----------
#define KS_STRIDE 68
#define VT_STRIDE 132
#define PS_STRIDE 132
#define ATTN_SMEM ((128*68 + 64*132 + 128*132 + 128*68) * 4)

__global__ __launch_bounds__(256) void attn_tc(
    const float* __restrict__ Q, const float* __restrict__ kf,
    const float* __restrict__ vf, float* __restrict__ O)
{
    extern __shared__ uint32_t smu[];
    uint32_t* Ks = smu;                       // [128][68]
    uint32_t* Vt = Ks + 128*KS_STRIDE;        // [64][132]
    uint32_t* Ps = Vt + 64*VT_STRIDE;         // [128][132]
    uint32_t* Qs = Ps + 128*PS_STRIDE;        // [128][68]

    const int t = threadIdx.x;
    const int warp = t >> 5, lane = t & 31;
    const int group = lane >> 2, tid4 = lane & 3;
    const int qb = blockIdx.x, h = blockIdx.y, b = blockIdx.z;

    const float* kfp = kf + (long)(b*H_ + h) * L_ * D_;
    const float* vfp = vf + (long)(b*H_ + h) * L_ * D_;

    for (int i = t*4; i < L_*D_; i += 1024) {
        float4 v = *reinterpret_cast<const float4*>(kfp + i);
        int k = i >> 6, d = i & 63;
        uint32_t* dst = &Ks[k*KS_STRIDE + d];
        dst[0]=f2tf(v.x); dst[1]=f2tf(v.y); dst[2]=f2tf(v.z); dst[3]=f2tf(v.w);
    }
    {
        int k = t & 127;
        int d0 = (t >> 7) * 32;
        #pragma unroll
        for (int d = 0; d < 32; d += 4) {
            float4 v = *reinterpret_cast<const float4*>(vfp + k*64 + d0 + d);
            Vt[(d0+d+0)*VT_STRIDE + k] = f2tf(v.x);
            Vt[(d0+d+1)*VT_STRIDE + k] = f2tf(v.y);
            Vt[(d0+d+2)*VT_STRIDE + k] = f2tf(v.z);
            Vt[(d0+d+3)*VT_STRIDE + k] = f2tf(v.w);
        }
    }
    {
        long base = ((long)b*N_ + qb*128) * C_ + h*D_;
        for (int i = t*4; i < 128*64; i += 1024) {
            int q = i >> 6, d = i & 63;
            float4 v = *reinterpret_cast<const float4*>(Q + base + (long)q*C_ + d);
            uint32_t* dst = &Qs[q*KS_STRIDE + d];
            dst[0]=f2tf(v.x); dst[1]=f2tf(v.y); dst[2]=f2tf(v.z); dst[3]=f2tf(v.w);
        }
    }
    __syncthreads();

    float accS[16][4];
    #pragma unroll
    for (int nt = 0; nt < 16; nt++)
        #pragma unroll
        for (int r = 0; r < 4; r++) accS[nt][r] = 0.f;

    const int qrow = warp*16;
    #pragma unroll
    for (int kf8 = 0; kf8 < 8; kf8++) {
        const int kk = kf8*8;
        uint32_t a0 = Qs[(qrow+group  )*KS_STRIDE + kk + tid4];
        uint32_t a1 = Qs[(qrow+group+8)*KS_STRIDE + kk + tid4];
        uint32_t a2 = Qs[(qrow+group  )*KS_STRIDE + kk + tid4 + 4];
        uint32_t a3 = Qs[(qrow+group+8)*KS_STRIDE + kk + tid4 + 4];
        #pragma unroll
        for (int nt = 0; nt < 16; nt++) {
            uint32_t b0 = Ks[(nt*8+group)*KS_STRIDE + kk + tid4];
            uint32_t b1 = Ks[(nt*8+group)*KS_STRIDE + kk + tid4 + 4];
            mma_tf32(accS[nt], a0, a1, a2, a3, b0, b1);
        }
    }

    const float scale = 0.125f;
    float m0 = -1e30f, m1 = -1e30f;
    #pragma unroll
    for (int nt = 0; nt < 16; nt++) {
        accS[nt][0] *= scale; accS[nt][1] *= scale;
        accS[nt][2] *= scale; accS[nt][3] *= scale;
        m0 = fmaxf(m0, fmaxf(accS[nt][0], accS[nt][1]));
        m1 = fmaxf(m1, fmaxf(accS[nt][2], accS[nt][3]));
    }
    m0 = fmaxf(m0, __shfl_xor_sync(0xffffffff, m0, 1));
    m0 = fmaxf(m0, __shfl_xor_sync(0xffffffff, m0, 2));
    m1 = fmaxf(m1, __shfl_xor_sync(0xffffffff, m1, 1));
    m1 = fmaxf(m1, __shfl_xor_sync(0xffffffff, m1, 2));

    float l0 = 0.f, l1 = 0.f;
    #pragma unroll
    for (int nt = 0; nt < 16; nt++) {
        accS[nt][0] = expf(accS[nt][0] - m0);
        accS[nt][1] = expf(accS[nt][1] - m0);
        accS[nt][2] = expf(accS[nt][2] - m1);
        accS[nt][3] = expf(accS[nt][3] - m1);
        l0 += accS[nt][0] + accS[nt][1];
        l1 += accS[nt][2] + accS[nt][3];
    }
    l0 += __shfl_xor_sync(0xffffffff, l0, 1);
    l0 += __shfl_xor_sync(0xffffffff, l0, 2);
    l1 += __shfl_xor_sync(0xffffffff, l1, 1);
    l1 += __shfl_xor_sync(0xffffffff, l1, 2);
    float rl0 = 1.f / l0, rl1 = 1.f / l1;

    #pragma unroll
    for (int nt = 0; nt < 16; nt++) {
        int col = nt*8 + tid4*2;
        uint2 p0, p1;
        p0.x = f2tf(accS[nt][0]*rl0); p0.y = f2tf(accS[nt][1]*rl0);
        p1.x = f2tf(accS[nt][2]*rl1); p1.y = f2tf(accS[nt][3]*rl1);
        *reinterpret_cast<uint2*>(&Ps[(qrow+group  )*PS_STRIDE + col]) = p0;
        *reinterpret_cast<uint2*>(&Ps[(qrow+group+8)*PS_STRIDE + col]) = p1;
    }
    __syncwarp();

    float accO[8][4];
    #pragma unroll
    for (int nt = 0; nt < 8; nt++)
        #pragma unroll
        for (int r = 0; r < 4; r++) accO[nt][r] = 0.f;

    #pragma unroll
    for (int kf8 = 0; kf8 < 16; kf8++) {
        const int kk = kf8*8;
        uint32_t a0 = Ps[(qrow+group  )*PS_STRIDE + kk + tid4];
        uint32_t a1 = Ps[(qrow+group+8)*PS_STRIDE + kk + tid4];
        uint32_t a2 = Ps[(qrow+group  )*PS_STRIDE + kk + tid4 + 4];
        uint32_t a3 = Ps[(qrow+group+8)*PS_STRIDE + kk + tid4 + 4];
        #pragma unroll
        for (int nt = 0; nt < 8; nt++) {
            uint32_t b0 = Vt[(nt*8+group)*VT_STRIDE + kk + tid4];
            uint32_t b1 = Vt[(nt*8+group)*VT_STRIDE + kk + tid4 + 4];
            mma_tf32(accO[nt], a0, a1, a2, a3, b0, b1);
        }
    }

    long row0 = (long)b*N_ + qb*128 + qrow + group;
    #pragma unroll
    for (int nt = 0; nt < 8; nt++) {
        int col = h*D_ + nt*8 + tid4*2;
        float2 o0, o1;
        o0.x = accO[nt][0]; o0.y = accO[nt][1];
        o1.x = accO[nt][2]; o1.y = accO[nt][3];
        *reinterpret_cast<float2*>(O + row0*C_ + col) = o0;
        *reinterpret_cast<float2*>(O + (row0+8)*C_ + col) = o1;
    }
}

// ---------------------------------------------------------------------------
extern "C" void kernel_launch(void* const* d_in, const int* in_sizes, int n_in,
                              void* d_out, int out_size)
{
    const float* x      = (const float*)d_in[0];
    const float* Wqkv   = (const float*)d_in[1];
    const float* bqkv   = (const float*)d_in[2];
    const float* E_k    = (const float*)d_in[3];
    const float* E_v    = (const float*)d_in[4];
    const float* Wproj  = (const float*)d_in[5];
    const float* bproj  = (const float*)d_in[6];
    const float* k_bank = (const float*)d_in[7];
    const float* v_bank = (const float*)d_in[8];

    float *Q, *xp, *KV, *kf, *vf, *ao;
    cudaGetSymbolAddress((void**)&Q,  g_Q);
    cudaGetSymbolAddress((void**)&xp, g_xp);
    cudaGetSymbolAddress((void**)&KV, g_KV);
    cudaGetSymbolAddress((void**)&kf, g_kf);
    cudaGetSymbolAddress((void**)&vf, g_vf);
    cudaGetSymbolAddress((void**)&ao, g_ao);

    cudaFuncSetAttribute(attn_tc,
                         cudaFuncAttributeMaxDynamicSharedMemorySize, ATTN_SMEM);

    // 1) pooled tokens (first 128 only are ever used)
    pool_kernel<<<(B_*L_*C_/4 + 255)/256, 256>>>(x, xp);

    // 2) Q = x @ Wqkv[:,0:768] + bqkv[0:768]
    hgemm<<<dim3(C_/128, B_*N_/128), 256>>>(x, Wqkv, bqkv, Q, C_, C_, 3*C_, C_);

    // 3) KV = xp @ Wqkv[:,768:2304] + bqkv[768:]
    hgemm<<<dim3(2*C_/128, B_*L_/128), 256>>>(xp, Wqkv + C_, bqkv + C_, KV,
                                              C_, C_, 3*C_, 2*C_);

    // 4) compress + bank concat
    kvcompress<<<dim3(2, H_, B_), 256>>>(KV, E_k, E_v, k_bank, v_bank, kf, vf);

    // 5) tensor-core attention
    attn_tc<<<dim3(N_/128, H_, B_), 256, ATTN_SMEM>>>(Q, kf, vf, ao);

    // 6) out = ao @ Wproj + bproj
    hgemm<<<dim3(C_/128, B_*N_/128), 256>>>(ao, Wproj, bproj, (float*)d_out,
                                            C_, C_, C_, C_);
}

// round 6
// speedup vs baseline: 1.5775x; 1.1198x over previous
#include <cuda_runtime.h>
#include <cuda_fp16.h>
#include <math.h>
#include <stdint.h>

#define B_  32
#define N_  1024
#define C_  768
#define H_  12
#define D_  64
#define L_  128

// ---------------- scratch (device globals: no allocations allowed) ----------
__device__ __half g_xh [B_*N_*C_];      // x in fp16
__device__ __half g_Wh [C_*3*C_];       // Wqkv in fp16
__device__ __half g_Wph[C_*C_];         // Wproj in fp16
__device__ __half g_Qh [B_*N_*C_];      // Q projection, fp16
__device__ __half g_xph[B_*L_*C_];      // pooled tokens, fp16
__device__ float  g_KV [B_*L_*2*C_];    // K|V projections (fp32 for kvcompress)
__device__ float  g_kf [B_*H_*L_*D_];   // k_full
__device__ float  g_vf [B_*H_*L_*D_];   // v_full
__device__ __half g_ao [B_*N_*C_];      // attention output, fp16

__device__ __forceinline__ unsigned f2tf(float f) {
    unsigned u;
    asm("cvt.rna.tf32.f32 %0, %1;" : "=r"(u) : "f"(f));
    return u;
}

__device__ __forceinline__ void mma_tf32(
    float* c, uint32_t a0, uint32_t a1, uint32_t a2, uint32_t a3,
    uint32_t b0, uint32_t b1)
{
    asm volatile(
        "mma.sync.aligned.m16n8k8.row.col.f32.tf32.tf32.f32 "
        "{%0,%1,%2,%3}, {%4,%5,%6,%7}, {%8,%9}, {%0,%1,%2,%3};"
        : "+f"(c[0]), "+f"(c[1]), "+f"(c[2]), "+f"(c[3])
        : "r"(a0), "r"(a1), "r"(a2), "r"(a3), "r"(b0), "r"(b1));
}

__device__ __forceinline__ void mma_f16(
    float* c, uint32_t a0, uint32_t a1, uint32_t a2, uint32_t a3,
    uint32_t b0, uint32_t b1)
{
    asm volatile(
        "mma.sync.aligned.m16n8k16.row.col.f32.f16.f16.f32 "
        "{%0,%1,%2,%3}, {%4,%5,%6,%7}, {%8,%9}, {%0,%1,%2,%3};"
        : "+f"(c[0]), "+f"(c[1]), "+f"(c[2]), "+f"(c[3])
        : "r"(a0), "r"(a1), "r"(a2), "r"(a3), "r"(b0), "r"(b1));
}

__device__ __forceinline__ void cp16(uint32_t saddr, const void* g) {
    asm volatile("cp.async.ca.shared.global [%0], [%1], 16;"
                 :: "r"(saddr), "l"(g));
}

// ---------------- fp32 -> fp16 converter ------------------------------------
__global__ void f2h_kernel(const float* __restrict__ s, __half* __restrict__ d,
                           int n4)
{
    int i = blockIdx.x * blockDim.x + threadIdx.x;
    if (i >= n4) return;
    float4 v = *reinterpret_cast<const float4*>(s + (long)i*4);
    __half2 h0 = __float22half2_rn(make_float2(v.x, v.y));
    __half2 h1 = __float22half2_rn(make_float2(v.z, v.w));
    uint2 o;
    o.x = *reinterpret_cast<uint32_t*>(&h0);
    o.y = *reinterpret_cast<uint32_t*>(&h1);
    *reinterpret_cast<uint2*>(d + (long)i*4) = o;
}

// ---------------- pooling -> fp16: xp[b,p,c] = .5*(x[2p]+x[2p+1]) -----------
__global__ void pool_kernel(const float* __restrict__ x, __half* __restrict__ xp)
{
    int i = blockIdx.x * blockDim.x + threadIdx.x;      // 4-elem index
    const int TOT4 = B_*L_*C_/4;
    if (i >= TOT4) return;
    int c4 = i % (C_/4);
    int p  = (i / (C_/4)) % L_;
    int b  = i / (C_/4 * L_);
    long base = (long)b*N_*C_ + (long)(2*p)*C_ + c4*4;
    float4 a = *reinterpret_cast<const float4*>(x + base);
    float4 c = *reinterpret_cast<const float4*>(x + base + C_);
    __half2 h0 = __float22half2_rn(make_float2(0.5f*(a.x+c.x), 0.5f*(a.y+c.y)));
    __half2 h1 = __float22half2_rn(make_float2(0.5f*(a.z+c.z), 0.5f*(a.w+c.w)));
    uint2 o;
    o.x = *reinterpret_cast<uint32_t*>(&h0);
    o.y = *reinterpret_cast<uint32_t*>(&h1);
    *reinterpret_cast<uint2*>(xp + (long)i*4) = o;
}

// -------- fp16 GEMM, cp.async double-buffered: C = A*B + bias ---------------
// A,B fp16. 128x128 tile, BK=32, 256 threads, warp tile 64x32. 2 CTAs/SM.
#define AH_STR 40      // halves per A row (32 data + 8 pad)
#define BHH_STR 136    // halves per B row (128 data + 8 pad)

__global__ __launch_bounds__(256, 2) void hgemm(
    const __half* __restrict__ A, const __half* __restrict__ Bm,
    const float* __restrict__ bias, void* __restrict__ Cv,
    int K, int lda, int ldb, int ldc, int half_out)
{
    __shared__ __half Ah[2][128*AH_STR];
    __shared__ __half Bh[2][32*BHH_STR];

    const int t    = threadIdx.x;
    const int warp = t >> 5;
    const int lane = t & 31;
    const int group = lane >> 2;
    const int tid4  = lane & 3;
    const int wm = (warp & 1) * 64;
    const int wn = (warp >> 1) * 32;

    const int bm = blockIdx.y * 128, bn = blockIdx.x * 128;

    float acc[4][4][4];
    #pragma unroll
    for (int mf = 0; mf < 4; mf++)
        #pragma unroll
        for (int nf = 0; nf < 4; nf++)
            #pragma unroll
            for (int r = 0; r < 4; r++) acc[mf][nf][r] = 0.f;

    const uint32_t aBase0 = (uint32_t)__cvta_generic_to_shared(&Ah[0][0]);
    const uint32_t aBase1 = (uint32_t)__cvta_generic_to_shared(&Ah[1][0]);
    const uint32_t bBase0 = (uint32_t)__cvta_generic_to_shared(&Bh[0][0]);
    const uint32_t bBase1 = (uint32_t)__cvta_generic_to_shared(&Bh[1][0]);

    // per-thread copy assignments
    const int arow0 = t >> 2;              // c = t        : rows 0..63
    const int aoff0 = (t & 3) * 8;
    const int arow1 = (t + 256) >> 2;      // rows 64..127
    const int aoff1 = aoff0;
    const int brow0 = t >> 4;              // rows 0..15
    const int boff0 = (t & 15) * 8;
    const int brow1 = (t + 256) >> 4;      // rows 16..31
    const int boff1 = boff0;

    const int ns = K >> 5;

    // prologue: slab 0 -> buffer 0
    {
        cp16(aBase0 + (arow0*AH_STR + aoff0)*2,
             A + (long)(bm + arow0)*lda + aoff0);
        cp16(aBase0 + (arow1*AH_STR + aoff1)*2,
             A + (long)(bm + arow1)*lda + aoff1);
        cp16(bBase0 + (brow0*BHH_STR + boff0)*2,
             Bm + (long)brow0*ldb + bn + boff0);
        cp16(bBase0 + (brow1*BHH_STR + boff1)*2,
             Bm + (long)brow1*ldb + bn + boff1);
        asm volatile("cp.async.commit_group;");
    }

    for (int i = 0; i < ns; i++) {
        const int k0 = i << 5;
        const int buf = i & 1;
        asm volatile("cp.async.wait_all;" ::: "memory");
        __syncthreads();

        if (i + 1 < ns) {
            const int kn = k0 + 32;
            const uint32_t aB = buf ? aBase0 : aBase1;
            const uint32_t bB = buf ? bBase0 : bBase1;
            cp16(aB + (arow0*AH_STR + aoff0)*2,
                 A + (long)(bm + arow0)*lda + kn + aoff0);
            cp16(aB + (arow1*AH_STR + aoff1)*2,
                 A + (long)(bm + arow1)*lda + kn + aoff1);
            cp16(bB + (brow0*BHH_STR + boff0)*2,
                 Bm + (long)(kn + brow0)*ldb + bn + boff0);
            cp16(bB + (brow1*BHH_STR + boff1)*2,
                 Bm + (long)(kn + brow1)*ldb + bn + boff1);
            asm volatile("cp.async.commit_group;");
        }

        const uint32_t* Awb = reinterpret_cast<const uint32_t*>(Ah[buf]);
        const __half*   Bhb = Bh[buf];

        #pragma unroll
        for (int ks = 0; ks < 2; ks++) {
            const int kw = ks * 8;            // word offset in A row
            const int kb = ks * 16;           // half row offset in B
            uint32_t a[4][4], b[4][2];
            #pragma unroll
            for (int mf = 0; mf < 4; mf++) {
                int r0 = wm + mf*16 + group;
                a[mf][0] = Awb[(r0    )*(AH_STR/2) + kw + tid4];
                a[mf][1] = Awb[(r0 + 8)*(AH_STR/2) + kw + tid4];
                a[mf][2] = Awb[(r0    )*(AH_STR/2) + kw + tid4 + 4];
                a[mf][3] = Awb[(r0 + 8)*(AH_STR/2) + kw + tid4 + 4];
            }
            #pragma unroll
            for (int nf = 0; nf < 4; nf++) {
                int cc = wn + nf*8 + group;
                __half2 b0 = __halves2half2(
                    Bhb[(kb + 2*tid4    )*BHH_STR + cc],
                    Bhb[(kb + 2*tid4 + 1)*BHH_STR + cc]);
                __half2 b1 = __halves2half2(
                    Bhb[(kb + 2*tid4 + 8)*BHH_STR + cc],
                    Bhb[(kb + 2*tid4 + 9)*BHH_STR + cc]);
                b[nf][0] = *reinterpret_cast<uint32_t*>(&b0);
                b[nf][1] = *reinterpret_cast<uint32_t*>(&b1);
            }
            #pragma unroll
            for (int mf = 0; mf < 4; mf++)
                #pragma unroll
                for (int nf = 0; nf < 4; nf++)
                    mma_f16(acc[mf][nf], a[mf][0], a[mf][1], a[mf][2], a[mf][3],
                            b[nf][0], b[nf][1]);
        }
        __syncthreads();
    }

    // epilogue
    if (half_out) {
        __half* C = reinterpret_cast<__half*>(Cv);
        #pragma unroll
        for (int mf = 0; mf < 4; mf++) {
            long r0 = bm + wm + mf*16 + group;
            #pragma unroll
            for (int nf = 0; nf < 4; nf++) {
                int c0 = bn + wn + nf*8 + tid4*2;
                float2 bi = *reinterpret_cast<const float2*>(bias + c0);
                __half2 h0 = __float22half2_rn(
                    make_float2(acc[mf][nf][0] + bi.x, acc[mf][nf][1] + bi.y));
                __half2 h1 = __float22half2_rn(
                    make_float2(acc[mf][nf][2] + bi.x, acc[mf][nf][3] + bi.y));
                *reinterpret_cast<__half2*>(C + r0*ldc + c0) = h0;
                *reinterpret_cast<__half2*>(C + (r0+8)*ldc + c0) = h1;
            }
        }
    } else {
        float* C = reinterpret_cast<float*>(Cv);
        #pragma unroll
        for (int mf = 0; mf < 4; mf++) {
            long r0 = bm + wm + mf*16 + group;
            #pragma unroll
            for (int nf = 0; nf < 4; nf++) {
                int c0 = bn + wn + nf*8 + tid4*2;
                float2 bi = *reinterpret_cast<const float2*>(bias + c0);
                float2 o0, o1;
                o0.x = acc[mf][nf][0] + bi.x; o0.y = acc[mf][nf][1] + bi.y;
                o1.x = acc[mf][nf][2] + bi.x; o1.y = acc[mf][nf][3] + bi.y;
                *reinterpret_cast<float2*>(C + r0*ldc + c0) = o0;
                *reinterpret_cast<float2*>(C + (r0+8)*ldc + c0) = o1;
            }
        }
    }
}

// ------------- kc/vc = E^T @ {K,V}_head, then append bank rows --------------
__global__ __launch_bounds__(256) void kvcompress(
    const float* __restrict__ KV, const float* __restrict__ E_k,
    const float* __restrict__ E_v, const float* __restrict__ k_bank,
    const float* __restrict__ v_bank, float* __restrict__ kf,
    float* __restrict__ vf)
{
    int which = blockIdx.x;      // 0: K, 1: V
    int h = blockIdx.y, b = blockIdx.z;
    const float* E    = which ? E_v : E_k;
    const float* bank = which ? v_bank : k_bank;
    float* out = (which ? vf : kf) + ((long)(b*H_ + h) * L_) * D_;

    __shared__ float Es[64][64];
    __shared__ float Ks[64][64];

    int tid = threadIdx.x;
    int d  = tid & 63;
    int cg = tid >> 6;
    float acc[16];
    #pragma unroll
    for (int i = 0; i < 16; i++) acc[i] = 0.f;

    for (int s0 = 0; s0 < L_; s0 += 64) {
        for (int i = tid*4; i < 64*64; i += 1024)
            *reinterpret_cast<float4*>(&Es[i>>6][i&63]) =
                *reinterpret_cast<const float4*>(E + (long)(s0 + (i>>6))*64 + (i&63));
        for (int i = tid; i < 64*16; i += 256) {
            int r = i >> 4, c4 = (i & 15)*4;
            *reinterpret_cast<float4*>(&Ks[r][c4]) =
                *reinterpret_cast<const float4*>(
                    KV + (long)b*L_*2*C_ + (long)(s0+r)*2*C_ + which*C_ + h*D_ + c4);
        }
        __syncthreads();
        for (int s = 0; s < 64; s++) {
            float kv = Ks[s][d];
            #pragma unroll
            for (int i = 0; i < 16; i++)
                acc[i] += Es[s][cg*16 + i] * kv;
        }
        __syncthreads();
    }
    #pragma unroll
    for (int i = 0; i < 16; i++)
        out[(long)(cg*16 + i)*D_ + d] = acc[i];

    for (int i = tid; i < 64*64; i += 256) {
        int r = i >> 6, dd = i & 63;
        out[(long)(64 + r)*D_ + dd] = bank[(long)b*64*C_ + (long)r*C_ + h*D_ + dd];
    }
}

// -------- tensor-core attention: 128 queries/block, 128 keys, tf32 ----------
// Q input fp16, output fp16.
#define KS_STRIDE 68
#define VT_STRIDE 132
#define PS_STRIDE 132
#define ATTN_SMEM ((128*68 + 64*132 + 128*132 + 128*68) * 4)

__global__ __launch_bounds__(256) void attn_tc(
    const __half* __restrict__ Q, const float* __restrict__ kf,
    const float* __restrict__ vf, __half* __restrict__ O)
{
    extern __shared__ uint32_t smu[];
    uint32_t* Ks = smu;                       // [128][68]
    uint32_t* Vt = Ks + 128*KS_STRIDE;        // [64][132]
    uint32_t* Ps = Vt + 64*VT_STRIDE;         // [128][132]
    uint32_t* Qs = Ps + 128*PS_STRIDE;        // [128][68]

    const int t = threadIdx.x;
    const int warp = t >> 5, lane = t & 31;
    const int group = lane >> 2, tid4 = lane & 3;
    const int qb = blockIdx.x, h = blockIdx.y, b = blockIdx.z;

    const float* kfp = kf + (long)(b*H_ + h) * L_ * D_;
    const float* vfp = vf + (long)(b*H_ + h) * L_ * D_;

    for (int i = t*4; i < L_*D_; i += 1024) {
        float4 v = *reinterpret_cast<const float4*>(kfp + i);
        int k = i >> 6, d = i & 63;
        uint32_t* dst = &Ks[k*KS_STRIDE + d];
        dst[0]=f2tf(v.x); dst[1]=f2tf(v.y); dst[2]=f2tf(v.z); dst[3]=f2tf(v.w);
    }
    {
        int k = t & 127;
        int d0 = (t >> 7) * 32;
        #pragma unroll
        for (int d = 0; d < 32; d += 4) {
            float4 v = *reinterpret_cast<const float4*>(vfp + k*64 + d0 + d);
            Vt[(d0+d+0)*VT_STRIDE + k] = f2tf(v.x);
            Vt[(d0+d+1)*VT_STRIDE + k] = f2tf(v.y);
            Vt[(d0+d+2)*VT_STRIDE + k] = f2tf(v.z);
            Vt[(d0+d+3)*VT_STRIDE + k] = f2tf(v.w);
        }
    }
    {
        long base = ((long)b*N_ + qb*128) * C_ + h*D_;
        for (int i = t*8; i < 128*64; i += 2048) {
            int q = i >> 6, d = i & 63;
            uint4 raw = *reinterpret_cast<const uint4*>(Q + base + (long)q*C_ + d);
            const __half2* hp = reinterpret_cast<const __half2*>(&raw);
            uint32_t* dst = &Qs[q*KS_STRIDE + d];
            #pragma unroll
            for (int j = 0; j < 4; j++) {
                float2 f = __half22float2(hp[j]);
                dst[2*j]   = f2tf(f.x);
                dst[2*j+1] = f2tf(f.y);
            }
        }
    }
    __syncthreads();

    float accS[16][4];
    #pragma unroll
    for (int nt = 0; nt < 16; nt++)
        #pragma unroll
        for (int r = 0; r < 4; r++) accS[nt][r] = 0.f;

    const int qrow = warp*16;
    #pragma unroll
    for (int kf8 = 0; kf8 < 8; kf8++) {
        const int kk = kf8*8;
        uint32_t a0 = Qs[(qrow+group  )*KS_STRIDE + kk + tid4];
        uint32_t a1 = Qs[(qrow+group+8)*KS_STRIDE + kk + tid4];
        uint32_t a2 = Qs[(qrow+group  )*KS_STRIDE + kk + tid4 + 4];
        uint32_t a3 = Qs[(qrow+group+8)*KS_STRIDE + kk + tid4 + 4];
        #pragma unroll
        for (int nt = 0; nt < 16; nt++) {
            uint32_t b0 = Ks[(nt*8+group)*KS_STRIDE + kk + tid4];
            uint32_t b1 = Ks[(nt*8+group)*KS_STRIDE + kk + tid4 + 4];
            mma_tf32(accS[nt], a0, a1, a2, a3, b0, b1);
        }
    }

    const float scale = 0.125f;
    float m0 = -1e30f, m1 = -1e30f;
    #pragma unroll
    for (int nt = 0; nt < 16; nt++) {
        accS[nt][0] *= scale; accS[nt][1] *= scale;
        accS[nt][2] *= scale; accS[nt][3] *= scale;
        m0 = fmaxf(m0, fmaxf(accS[nt][0], accS[nt][1]));
        m1 = fmaxf(m1, fmaxf(accS[nt][2], accS[nt][3]));
    }
    m0 = fmaxf(m0, __shfl_xor_sync(0xffffffff, m0, 1));
    m0 = fmaxf(m0, __shfl_xor_sync(0xffffffff, m0, 2));
    m1 = fmaxf(m1, __shfl_xor_sync(0xffffffff, m1, 1));
    m1 = fmaxf(m1, __shfl_xor_sync(0xffffffff, m1, 2));

    float l0 = 0.f, l1 = 0.f;
    #pragma unroll
    for (int nt = 0; nt < 16; nt++) {
        accS[nt][0] = expf(accS[nt][0] - m0);
        accS[nt][1] = expf(accS[nt][1] - m0);
        accS[nt][2] = expf(accS[nt][2] - m1);
        accS[nt][3] = expf(accS[nt][3] - m1);
        l0 += accS[nt][0] + accS[nt][1];
        l1 += accS[nt][2] + accS[nt][3];
    }
    l0 += __shfl_xor_sync(0xffffffff, l0, 1);
    l0 += __shfl_xor_sync(0xffffffff, l0, 2);
    l1 += __shfl_xor_sync(0xffffffff, l1, 1);
    l1 += __shfl_xor_sync(0xffffffff, l1, 2);
    float rl0 = 1.f / l0, rl1 = 1.f / l1;

    #pragma unroll
    for (int nt = 0; nt < 16; nt++) {
        int col = nt*8 + tid4*2;
        uint2 p0, p1;
        p0.x = f2tf(accS[nt][0]*rl0); p0.y = f2tf(accS[nt][1]*rl0);
        p1.x = f2tf(accS[nt][2]*rl1); p1.y = f2tf(accS[nt][3]*rl1);
        *reinterpret_cast<uint2*>(&Ps[(qrow+group  )*PS_STRIDE + col]) = p0;
        *reinterpret_cast<uint2*>(&Ps[(qrow+group+8)*PS_STRIDE + col]) = p1;
    }
    __syncwarp();

    float accO[8][4];
    #pragma unroll
    for (int nt = 0; nt < 8; nt++)
        #pragma unroll
        for (int r = 0; r < 4; r++) accO[nt][r] = 0.f;

    #pragma unroll
    for (int kf8 = 0; kf8 < 16; kf8++) {
        const int kk = kf8*8;
        uint32_t a0 = Ps[(qrow+group  )*PS_STRIDE + kk + tid4];
        uint32_t a1 = Ps[(qrow+group+8)*PS_STRIDE + kk + tid4];
        uint32_t a2 = Ps[(qrow+group  )*PS_STRIDE + kk + tid4 + 4];
        uint32_t a3 = Ps[(qrow+group+8)*PS_STRIDE + kk + tid4 + 4];
        #pragma unroll
        for (int nt = 0; nt < 8; nt++) {
            uint32_t b0 = Vt[(nt*8+group)*VT_STRIDE + kk + tid4];
            uint32_t b1 = Vt[(nt*8+group)*VT_STRIDE + kk + tid4 + 4];
            mma_tf32(accO[nt], a0, a1, a2, a3, b0, b1);
        }
    }

    long row0 = (long)b*N_ + qb*128 + qrow + group;
    #pragma unroll
    for (int nt = 0; nt < 8; nt++) {
        int col = h*D_ + nt*8 + tid4*2;
        __half2 h0 = __float22half2_rn(make_float2(accO[nt][0], accO[nt][1]));
        __half2 h1 = __float22half2_rn(make_float2(accO[nt][2], accO[nt][3]));
        *reinterpret_cast<__half2*>(O + row0*C_ + col) = h0;
        *reinterpret_cast<__half2*>(O + (row0+8)*C_ + col) = h1;
    }
}

// ---------------------------------------------------------------------------
extern "C" void kernel_launch(void* const* d_in, const int* in_sizes, int n_in,
                              void* d_out, int out_size)
{
    const float* x      = (const float*)d_in[0];
    const float* Wqkv   = (const float*)d_in[1];
    const float* bqkv   = (const float*)d_in[2];
    const float* E_k    = (const float*)d_in[3];
    const float* E_v    = (const float*)d_in[4];
    const float* Wproj  = (const float*)d_in[5];
    const float* bproj  = (const float*)d_in[6];
    const float* k_bank = (const float*)d_in[7];
    const float* v_bank = (const float*)d_in[8];

    __half *xh, *Wh, *Wph, *Qh, *xph, *ao;
    float *KV, *kf, *vf;
    cudaGetSymbolAddress((void**)&xh,  g_xh);
    cudaGetSymbolAddress((void**)&Wh,  g_Wh);
    cudaGetSymbolAddress((void**)&Wph, g_Wph);
    cudaGetSymbolAddress((void**)&Qh,  g_Qh);
    cudaGetSymbolAddress((void**)&xph, g_xph);
    cudaGetSymbolAddress((void**)&KV,  g_KV);
    cudaGetSymbolAddress((void**)&kf,  g_kf);
    cudaGetSymbolAddress((void**)&vf,  g_vf);
    cudaGetSymbolAddress((void**)&ao,  g_ao);

    cudaFuncSetAttribute(attn_tc,
                         cudaFuncAttributeMaxDynamicSharedMemorySize, ATTN_SMEM);

    // 0) fp16 conversions
    f2h_kernel<<<(B_*N_*C_/4 + 255)/256, 256>>>(x, xh, B_*N_*C_/4);
    f2h_kernel<<<(C_*3*C_/4 + 255)/256, 256>>>(Wqkv, Wh, C_*3*C_/4);
    f2h_kernel<<<(C_*C_/4 + 255)/256, 256>>>(Wproj, Wph, C_*C_/4);

    // 1) pooled tokens -> fp16
    pool_kernel<<<(B_*L_*C_/4 + 255)/256, 256>>>(x, xph);

    // 2) Q = x @ Wqkv[:,0:768] + bqkv  -> fp16
    hgemm<<<dim3(C_/128, B_*N_/128), 256>>>(xh, Wh, bqkv, Qh,
                                            C_, C_, 3*C_, C_, 1);

    // 3) KV = xp @ Wqkv[:,768:2304] + bqkv[768:] -> fp32
    hgemm<<<dim3(2*C_/128, B_*L_/128), 256>>>(xph, Wh + C_, bqkv + C_, KV,
                                              C_, C_, 3*C_, 2*C_, 0);

    // 4) compress + bank concat
    kvcompress<<<dim3(2, H_, B_), 256>>>(KV, E_k, E_v, k_bank, v_bank, kf, vf);

    // 5) tensor-core attention (fp16 in/out)
    attn_tc<<<dim3(N_/128, H_, B_), 256, ATTN_SMEM>>>(Qh, kf, vf, ao);

    // 6) out = ao @ Wproj + bproj -> fp32
    hgemm<<<dim3(C_/128, B_*N_/128), 256>>>(ao, Wph, bproj, (float*)d_out,
                                            C_, C_, C_, C_, 0);
}

// round 7
// speedup vs baseline: 1.8659x; 1.1828x over previous
#include <cuda_runtime.h>
#include <cuda_fp16.h>
#include <math.h>
#include <stdint.h>

#define B_  32
#define N_  1024
#define C_  768
#define H_  12
#define D_  64
#define L_  128

// ---------------- scratch (device globals: no allocations allowed) ----------
__device__ __half g_xh [B_*N_*C_];      // x in fp16
__device__ __half g_Wqt[3*C_*C_];       // Wqkv^T  [2304][768] fp16
__device__ __half g_Wpt[C_*C_];         // Wproj^T [768][768] fp16
__device__ __half g_Qh [B_*N_*C_];      // Q projection, fp16
__device__ __half g_xph[B_*L_*C_];      // pooled tokens, fp16
__device__ __half g_KVh[B_*L_*2*C_];    // K|V projections, fp16
__device__ __half g_kfh[B_*H_*L_*D_];   // k_full fp16 [bh][128][64]
__device__ __half g_vth[B_*H_*D_*L_];   // v_full fp16 TRANSPOSED [bh][64][128]
__device__ __half g_ao [B_*N_*C_];      // attention output, fp16

__device__ __forceinline__ void mma_f16(
    float* c, uint32_t a0, uint32_t a1, uint32_t a2, uint32_t a3,
    uint32_t b0, uint32_t b1)
{
    asm volatile(
        "mma.sync.aligned.m16n8k16.row.col.f32.f16.f16.f32 "
        "{%0,%1,%2,%3}, {%4,%5,%6,%7}, {%8,%9}, {%0,%1,%2,%3};"
        : "+f"(c[0]), "+f"(c[1]), "+f"(c[2]), "+f"(c[3])
        : "r"(a0), "r"(a1), "r"(a2), "r"(a3), "r"(b0), "r"(b1));
}

__device__ __forceinline__ void cp16(uint32_t saddr, const void* g) {
    asm volatile("cp.async.ca.shared.global [%0], [%1], 16;"
                 :: "r"(saddr), "l"(g));
}

// ---------------- fp32 -> fp16 converter ------------------------------------
__global__ void f2h_kernel(const float* __restrict__ s, __half* __restrict__ d,
                           int n4)
{
    int i = blockIdx.x * blockDim.x + threadIdx.x;
    if (i >= n4) return;
    float4 v = *reinterpret_cast<const float4*>(s + (long)i*4);
    __half2 h0 = __float22half2_rn(make_float2(v.x, v.y));
    __half2 h1 = __float22half2_rn(make_float2(v.z, v.w));
    uint2 o;
    o.x = *reinterpret_cast<uint32_t*>(&h0);
    o.y = *reinterpret_cast<uint32_t*>(&h1);
    *reinterpret_cast<uint2*>(d + (long)i*4) = o;
}

// ---------------- fp32 -> fp16 transpose: Wt[c][r] = W[r][c] ----------------
__global__ void f2h_T(const float* __restrict__ W, __half* __restrict__ Wt,
                      int rows, int cols)
{
    __shared__ float s[32][33];
    int c0 = blockIdx.x*32, r0 = blockIdx.y*32;
    int tx = threadIdx.x, ty = threadIdx.y;   // 32 x 8
    #pragma unroll
    for (int i = 0; i < 32; i += 8)
        s[ty+i][tx] = W[(long)(r0+ty+i)*cols + c0+tx];
    __syncthreads();
    #pragma unroll
    for (int i = 0; i < 32; i += 8)
        Wt[(long)(c0+ty+i)*rows + r0+tx] = __float2half_rn(s[tx][ty+i]);
}

// ---------------- pooling -> fp16: xp[b,p,c] = .5*(x[2p]+x[2p+1]) -----------
__global__ void pool_kernel(const float* __restrict__ x, __half* __restrict__ xp)
{
    int i = blockIdx.x * blockDim.x + threadIdx.x;      // 4-elem index
    const int TOT4 = B_*L_*C_/4;
    if (i >= TOT4) return;
    int c4 = i % (C_/4);
    int p  = (i / (C_/4)) % L_;
    int b  = i / (C_/4 * L_);
    long base = (long)b*N_*C_ + (long)(2*p)*C_ + c4*4;
    float4 a = *reinterpret_cast<const float4*>(x + base);
    float4 c = *reinterpret_cast<const float4*>(x + base + C_);
    __half2 h0 = __float22half2_rn(make_float2(0.5f*(a.x+c.x), 0.5f*(a.y+c.y)));
    __half2 h1 = __float22half2_rn(make_float2(0.5f*(a.z+c.z), 0.5f*(a.w+c.w)));
    uint2 o;
    o.x = *reinterpret_cast<uint32_t*>(&h0);
    o.y = *reinterpret_cast<uint32_t*>(&h1);
    *reinterpret_cast<uint2*>(xp + (long)i*4) = o;
}

// -------- fp16 GEMM, cp.async double-buffered: C = A*Bt^T + bias ------------
// A [M,K] fp16 row-major; Bt [N,K] fp16 row-major (pre-transposed weights).
// 128x128 tile, BK=32, 256 threads, warp tile 64x32, 2 CTAs/SM.
#define TH_STR 40      // halves per smem row (32 data + 8 pad); 20 words

__global__ __launch_bounds__(256, 2) void hgemm(
    const __half* __restrict__ A, const __half* __restrict__ Bt,
    const float* __restrict__ bias, void* __restrict__ Cv,
    int K, int lda, int ldbt, int ldc, int half_out)
{
    __shared__ __half Ah[2][128*TH_STR];
    __shared__ __half Bh[2][128*TH_STR];

    const int t    = threadIdx.x;
    const int warp = t >> 5;
    const int lane = t & 31;
    const int group = lane >> 2;
    const int tid4  = lane & 3;
    const int wm = (warp & 1) * 64;
    const int wn = (warp >> 1) * 32;

    const int bm = blockIdx.y * 128, bn = blockIdx.x * 128;

    float acc[4][4][4];
    #pragma unroll
    for (int mf = 0; mf < 4; mf++)
        #pragma unroll
        for (int nf = 0; nf < 4; nf++)
            #pragma unroll
            for (int r = 0; r < 4; r++) acc[mf][nf][r] = 0.f;

    const uint32_t aB0 = (uint32_t)__cvta_generic_to_shared(&Ah[0][0]);
    const uint32_t aB1 = (uint32_t)__cvta_generic_to_shared(&Ah[1][0]);
    const uint32_t bB0 = (uint32_t)__cvta_generic_to_shared(&Bh[0][0]);
    const uint32_t bB1 = (uint32_t)__cvta_generic_to_shared(&Bh[1][0]);

    // copy assignments: A rows t>>2 and (t>>2)+64, off (t&3)*8 halves
    //                   B rows t>>1, offs (t&1)*16 + {0,8}
    const int ar0 = t >> 2,        aof = (t & 3) * 8;
    const int ar1 = ar0 + 64;
    const int br  = t >> 1,        bof = (t & 1) * 16;

    const int ns = K >> 5;

    // prologue
    cp16(aB0 + (ar0*TH_STR + aof)*2, A + (long)(bm + ar0)*lda + aof);
    cp16(aB0 + (ar1*TH_STR + aof)*2, A + (long)(bm + ar1)*lda + aof);
    cp16(bB0 + (br*TH_STR + bof)*2,     Bt + (long)(bn + br)*ldbt + bof);
    cp16(bB0 + (br*TH_STR + bof + 8)*2, Bt + (long)(bn + br)*ldbt + bof + 8);
    asm volatile("cp.async.commit_group;");

    for (int i = 0; i < ns; i++) {
        const int buf = i & 1;
        asm volatile("cp.async.wait_all;" ::: "memory");
        __syncthreads();

        if (i + 1 < ns) {
            const int kn = (i + 1) << 5;
            const uint32_t aB = buf ? aB0 : aB1;
            const uint32_t bB = buf ? bB0 : bB1;
            cp16(aB + (ar0*TH_STR + aof)*2, A + (long)(bm + ar0)*lda + kn + aof);
            cp16(aB + (ar1*TH_STR + aof)*2, A + (long)(bm + ar1)*lda + kn + aof);
            cp16(bB + (br*TH_STR + bof)*2,     Bt + (long)(bn + br)*ldbt + kn + bof);
            cp16(bB + (br*TH_STR + bof + 8)*2, Bt + (long)(bn + br)*ldbt + kn + bof + 8);
            asm volatile("cp.async.commit_group;");
        }

        const uint32_t* Aw = reinterpret_cast<const uint32_t*>(Ah[buf]);
        const uint32_t* Bw = reinterpret_cast<const uint32_t*>(Bh[buf]);

        #pragma unroll
        for (int ks = 0; ks < 2; ks++) {
            const int kw = ks * 8;
            uint32_t a[4][4], b[4][2];
            #pragma unroll
            for (int mf = 0; mf < 4; mf++) {
                int r0 = wm + mf*16 + group;
                a[mf][0] = Aw[(r0    )*20 + kw + tid4];
                a[mf][1] = Aw[(r0 + 8)*20 + kw + tid4];
                a[mf][2] = Aw[(r0    )*20 + kw + tid4 + 4];
                a[mf][3] = Aw[(r0 + 8)*20 + kw + tid4 + 4];
            }
            #pragma unroll
            for (int nf = 0; nf < 4; nf++) {
                int cc = wn + nf*8 + group;
                b[nf][0] = Bw[cc*20 + kw + tid4];
                b[nf][1] = Bw[cc*20 + kw + tid4 + 4];
            }
            #pragma unroll
            for (int mf = 0; mf < 4; mf++)
                #pragma unroll
                for (int nf = 0; nf < 4; nf++)
                    mma_f16(acc[mf][nf], a[mf][0], a[mf][1], a[mf][2], a[mf][3],
                            b[nf][0], b[nf][1]);
        }
        __syncthreads();
    }

    if (half_out) {
        __half* C = reinterpret_cast<__half*>(Cv);
        #pragma unroll
        for (int mf = 0; mf < 4; mf++) {
            long r0 = bm + wm + mf*16 + group;
            #pragma unroll
            for (int nf = 0; nf < 4; nf++) {
                int c0 = bn + wn + nf*8 + tid4*2;
                float2 bi = *reinterpret_cast<const float2*>(bias + c0);
                __half2 h0 = __float22half2_rn(
                    make_float2(acc[mf][nf][0] + bi.x, acc[mf][nf][1] + bi.y));
                __half2 h1 = __float22half2_rn(
                    make_float2(acc[mf][nf][2] + bi.x, acc[mf][nf][3] + bi.y));
                *reinterpret_cast<__half2*>(C + r0*ldc + c0) = h0;
                *reinterpret_cast<__half2*>(C + (r0+8)*ldc + c0) = h1;
            }
        }
    } else {
        float* C = reinterpret_cast<float*>(Cv);
        #pragma unroll
        for (int mf = 0; mf < 4; mf++) {
            long r0 = bm + wm + mf*16 + group;
            #pragma unroll
            for (int nf = 0; nf < 4; nf++) {
                int c0 = bn + wn + nf*8 + tid4*2;
                float2 bi = *reinterpret_cast<const float2*>(bias + c0);
                float2 o0, o1;
                o0.x = acc[mf][nf][0] + bi.x; o0.y = acc[mf][nf][1] + bi.y;
                o1.x = acc[mf][nf][2] + bi.x; o1.y = acc[mf][nf][3] + bi.y;
                *reinterpret_cast<float2*>(C + r0*ldc + c0) = o0;
                *reinterpret_cast<float2*>(C + (r0+8)*ldc + c0) = o1;
            }
        }
    }
}

// ------ tensor-core kvcompress: out = E^T @ KV_head (64x64x128), + bank -----
// grid (2, H, B), 128 threads (4 warps). K output [k][d]; V output [d][k].
__global__ __launch_bounds__(128) void kvcompress(
    const __half* __restrict__ KV, const float* __restrict__ E_k,
    const float* __restrict__ E_v, const float* __restrict__ k_bank,
    const float* __restrict__ v_bank, __half* __restrict__ kf,
    __half* __restrict__ vt)
{
    __shared__ __half Et[64*136];   // [c][s], stride 136 halves (68 words)
    __shared__ __half Kt[64*136];   // [d][s]

    const int which = blockIdx.x, h = blockIdx.y, b = blockIdx.z;
    const float* E    = which ? E_v : E_k;
    const float* bank = which ? v_bank : k_bank;

    const int t = threadIdx.x;
    const int warp = t >> 5, lane = t & 31;
    const int group = lane >> 2, tid4 = lane & 3;

    // Et[c][s] = E[s][c]
    for (int i = t*4; i < 128*64; i += 512) {
        int s = i >> 6, c = i & 63;
        float4 v = *reinterpret_cast<const float4*>(E + s*64 + c);
        Et[(c+0)*136 + s] = __float2half_rn(v.x);
        Et[(c+1)*136 + s] = __float2half_rn(v.y);
        Et[(c+2)*136 + s] = __float2half_rn(v.z);
        Et[(c+3)*136 + s] = __float2half_rn(v.w);
    }
    // Kt[d][s] = KV[b][s][which*C + h*64 + d]
    const __half* kvp = KV + (long)b*L_*2*C_ + which*C_ + h*D_;
    for (int i = t*4; i < 128*64; i += 512) {
        int s = i >> 6, d = i & 63;
        uint2 raw = *reinterpret_cast<const uint2*>(kvp + (long)s*2*C_ + d);
        const __half* hp = reinterpret_cast<const __half*>(&raw);
        Kt[(d+0)*136 + s] = hp[0];
        Kt[(d+1)*136 + s] = hp[1];
        Kt[(d+2)*136 + s] = hp[2];
        Kt[(d+3)*136 + s] = hp[3];
    }
    __syncthreads();

    float acc[8][4];
    #pragma unroll
    for (int nf = 0; nf < 8; nf++)
        #pragma unroll
        for (int r = 0; r < 4; r++) acc[nf][r] = 0.f;

    const uint32_t* Ew = reinterpret_cast<const uint32_t*>(Et);
    const uint32_t* Kw = reinterpret_cast<const uint32_t*>(Kt);
    const int m0 = warp*16 + group;

    #pragma unroll
    for (int ks = 0; ks < 8; ks++) {
        const int kw = ks * 8;
        uint32_t a0 = Ew[(m0    )*68 + kw + tid4];
        uint32_t a1 = Ew[(m0 + 8)*68 + kw + tid4];
        uint32_t a2 = Ew[(m0    )*68 + kw + tid4 + 4];
        uint32_t a3 = Ew[(m0 + 8)*68 + kw + tid4 + 4];
        #pragma unroll
        for (int nf = 0; nf < 8; nf++) {
            uint32_t b0 = Kw[(nf*8+group)*68 + kw + tid4];
            uint32_t b1 = Kw[(nf*8+group)*68 + kw + tid4 + 4];
            mma_f16(acc[nf], a0, a1, a2, a3, b0, b1);
        }
    }

    const long bh = (long)(b*H_ + h);
    if (which == 0) {
        __half* out = kf + bh*L_*D_;            // [128][64]
        #pragma unroll
        for (int nf = 0; nf < 8; nf++) {
            int d = nf*8 + tid4*2;
            __half2 h0 = __float22half2_rn(make_float2(acc[nf][0], acc[nf][1]));
            __half2 h1 = __float22half2_rn(make_float2(acc[nf][2], acc[nf][3]));
            *reinterpret_cast<__half2*>(out + (m0  )*64 + d) = h0;
            *reinterpret_cast<__half2*>(out + (m0+8)*64 + d) = h1;
        }
        __syncthreads();
        for (int i = t*4; i < 64*64; i += 512) {
            int r = i >> 6, d = i & 63;
            float4 v = *reinterpret_cast<const float4*>(
                bank + (long)b*64*C_ + (long)r*C_ + h*D_ + d);
            __half2 h0 = __float22half2_rn(make_float2(v.x, v.y));
            __half2 h1 = __float22half2_rn(make_float2(v.z, v.w));
            *reinterpret_cast<__half2*>(out + (64+r)*64 + d) = h0;
            *reinterpret_cast<__half2*>(out + (64+r)*64 + d + 2) = h1;
        }
    } else {
        __half* out = vt + bh*D_*L_;            // [64][128] (d-major)
        #pragma unroll
        for (int nf = 0; nf < 8; nf++) {
            int d = nf*8 + tid4*2;
            out[(d  )*128 + m0    ] = __float2half_rn(acc[nf][0]);
            out[(d+1)*128 + m0    ] = __float2half_rn(acc[nf][1]);
            out[(d  )*128 + m0 + 8] = __float2half_rn(acc[nf][2]);
            out[(d+1)*128 + m0 + 8] = __float2half_rn(acc[nf][3]);
        }
        __syncthreads();
        for (int i = t*4; i < 64*64; i += 512) {
            int r = i >> 6, d = i & 63;
            float4 v = *reinterpret_cast<const float4*>(
                bank + (long)b*64*C_ + (long)r*C_ + h*D_ + d);
            out[(d  )*128 + 64 + r] = __float2half_rn(v.x);
            out[(d+1)*128 + 64 + r] = __float2half_rn(v.y);
            out[(d+2)*128 + 64 + r] = __float2half_rn(v.z);
            out[(d+3)*128 + 64 + r] = __float2half_rn(v.w);
        }
    }
}

// -------- fp16 tensor-core attention: 128 q/block, 128 keys -----------------
// smem strides in words: Q/K rows 36 (72 halves), V/P rows 68 (136 halves).
#define QS_W 36
#define VS_W 68
#define ATTN_SMEM ((128*QS_W + 64*VS_W + 128*VS_W + 128*QS_W) * 4)

__global__ __launch_bounds__(256, 2) void attn_tc(
    const __half* __restrict__ Q, const __half* __restrict__ kf,
    const __half* __restrict__ vt, __half* __restrict__ O)
{
    extern __shared__ uint32_t smu[];
    uint32_t* Ksw = smu;                      // [128][36]
    uint32_t* Vtw = Ksw + 128*QS_W;           // [64][68]
    uint32_t* Psw = Vtw + 64*VS_W;            // [128][68]
    uint32_t* Qsw = Psw + 128*VS_W;           // [128][36]

    const int t = threadIdx.x;
    const int warp = t >> 5, lane = t & 31;
    const int group = lane >> 2, tid4 = lane & 3;
    const int qb = blockIdx.x, h = blockIdx.y, b = blockIdx.z;

    const __half* kfp = kf + (long)(b*H_ + h) * L_ * D_;   // [128][64]
    const __half* vtp = vt + (long)(b*H_ + h) * D_ * L_;   // [64][128]

    // K: direct copy (8 halves per uint4)
    for (int i = t*8; i < L_*D_; i += 2048) {
        int k = i >> 6, d = i & 63;
        *reinterpret_cast<uint4*>(&Ksw[k*QS_W + (d>>1)]) =
            *reinterpret_cast<const uint4*>(kfp + i);
    }
    // V (already [d][k]): direct copy
    for (int i = t*8; i < D_*L_; i += 2048) {
        int d = i >> 7, k = i & 127;
        *reinterpret_cast<uint4*>(&Vtw[d*VS_W + (k>>1)]) =
            *reinterpret_cast<const uint4*>(vtp + i);
    }
    // Q: direct copy from strided rows
    {
        long base = ((long)b*N_ + qb*128) * C_ + h*D_;
        for (int i = t*8; i < 128*64; i += 2048) {
            int q = i >> 6, d = i & 63;
            *reinterpret_cast<uint4*>(&Qsw[q*QS_W + (d>>1)]) =
                *reinterpret_cast<const uint4*>(Q + base + (long)q*C_ + d);
        }
    }
    __syncthreads();

    // --- S = Q K^T (fp16 mma, 4 ksteps over d=64) ---
    float accS[16][4];
    #pragma unroll
    for (int nt = 0; nt < 16; nt++)
        #pragma unroll
        for (int r = 0; r < 4; r++) accS[nt][r] = 0.f;

    const int qrow = warp*16;
    #pragma unroll
    for (int ks = 0; ks < 4; ks++) {
        const int kw = ks * 8;
        uint32_t a0 = Qsw[(qrow+group  )*QS_W + kw + tid4];
        uint32_t a1 = Qsw[(qrow+group+8)*QS_W + kw + tid4];
        uint32_t a2 = Qsw[(qrow+group  )*QS_W + kw + tid4 + 4];
        uint32_t a3 = Qsw[(qrow+group+8)*QS_W + kw + tid4 + 4];
        #pragma unroll
        for (int nt = 0; nt < 16; nt++) {
            uint32_t b0 = Ksw[(nt*8+group)*QS_W + kw + tid4];
            uint32_t b1 = Ksw[(nt*8+group)*QS_W + kw + tid4 + 4];
            mma_f16(accS[nt], a0, a1, a2, a3, b0, b1);
        }
    }

    // --- softmax over 128 keys ---
    const float scale = 0.125f;
    float m0 = -1e30f, m1 = -1e30f;
    #pragma unroll
    for (int nt = 0; nt < 16; nt++) {
        accS[nt][0] *= scale; accS[nt][1] *= scale;
        accS[nt][2] *= scale; accS[nt][3] *= scale;
        m0 = fmaxf(m0, fmaxf(accS[nt][0], accS[nt][1]));
        m1 = fmaxf(m1, fmaxf(accS[nt][2], accS[nt][3]));
    }
    m0 = fmaxf(m0, __shfl_xor_sync(0xffffffff, m0, 1));
    m0 = fmaxf(m0, __shfl_xor_sync(0xffffffff, m0, 2));
    m1 = fmaxf(m1, __shfl_xor_sync(0xffffffff, m1, 1));
    m1 = fmaxf(m1, __shfl_xor_sync(0xffffffff, m1, 2));

    float l0 = 0.f, l1 = 0.f;
    #pragma unroll
    for (int nt = 0; nt < 16; nt++) {
        accS[nt][0] = expf(accS[nt][0] - m0);
        accS[nt][1] = expf(accS[nt][1] - m0);
        accS[nt][2] = expf(accS[nt][2] - m1);
        accS[nt][3] = expf(accS[nt][3] - m1);
        l0 += accS[nt][0] + accS[nt][1];
        l1 += accS[nt][2] + accS[nt][3];
    }
    l0 += __shfl_xor_sync(0xffffffff, l0, 1);
    l0 += __shfl_xor_sync(0xffffffff, l0, 2);
    l1 += __shfl_xor_sync(0xffffffff, l1, 1);
    l1 += __shfl_xor_sync(0xffffffff, l1, 2);
    float rl0 = 1.f / l0, rl1 = 1.f / l1;

    // --- store P (normalized) fp16 ---
    #pragma unroll
    for (int nt = 0; nt < 16; nt++) {
        __half2 p0 = __float22half2_rn(
            make_float2(accS[nt][0]*rl0, accS[nt][1]*rl0));
        __half2 p1 = __float22half2_rn(
            make_float2(accS[nt][2]*rl1, accS[nt][3]*rl1));
        Psw[(qrow+group  )*VS_W + nt*4 + tid4] = *reinterpret_cast<uint32_t*>(&p0);
        Psw[(qrow+group+8)*VS_W + nt*4 + tid4] = *reinterpret_cast<uint32_t*>(&p1);
    }
    __syncwarp();

    // --- O = P V (fp16 mma, 8 ksteps over 128 keys) ---
    float accO[8][4];
    #pragma unroll
    for (int nt = 0; nt < 8; nt++)
        #pragma unroll
        for (int r = 0; r < 4; r++) accO[nt][r] = 0.f;

    #pragma unroll
    for (int ks = 0; ks < 8; ks++) {
        const int kw = ks * 8;
        uint32_t a0 = Psw[(qrow+group  )*VS_W + kw + tid4];
        uint32_t a1 = Psw[(qrow+group+8)*VS_W + kw + tid4];
        uint32_t a2 = Psw[(qrow+group  )*VS_W + kw + tid4 + 4];
        uint32_t a3 = Psw[(qrow+group+8)*VS_W + kw + tid4 + 4];
        #pragma unroll
        for (int nt = 0; nt < 8; nt++) {
            uint32_t b0 = Vtw[(nt*8+group)*VS_W + kw + tid4];
            uint32_t b1 = Vtw[(nt*8+group)*VS_W + kw + tid4 + 4];
            mma_f16(accO[nt], a0, a1, a2, a3, b0, b1);
        }
    }

    long row0 = (long)b*N_ + qb*128 + qrow + group;
    #pragma unroll
    for (int nt = 0; nt < 8; nt++) {
        int col = h*D_ + nt*8 + tid4*2;
        __half2 h0 = __float22half2_rn(make_float2(accO[nt][0], accO[nt][1]));
        __half2 h1 = __float22half2_rn(make_float2(accO[nt][2], accO[nt][3]));
        *reinterpret_cast<__half2*>(O + row0*C_ + col) = h0;
        *reinterpret_cast<__half2*>(O + (row0+8)*C_ + col) = h1;
    }
}

// ---------------------------------------------------------------------------
extern "C" void kernel_launch(void* const* d_in, const int* in_sizes, int n_in,
                              void* d_out, int out_size)
{
    const float* x      = (const float*)d_in[0];
    const float* Wqkv   = (const float*)d_in[1];
    const float* bqkv   = (const float*)d_in[2];
    const float* E_k    = (const float*)d_in[3];
    const float* E_v    = (const float*)d_in[4];
    const float* Wproj  = (const float*)d_in[5];
    const float* bproj  = (const float*)d_in[6];
    const float* k_bank = (const float*)d_in[7];
    const float* v_bank = (const float*)d_in[8];

    __half *xh, *Wqt, *Wpt, *Qh, *xph, *KVh, *kfh, *vth, *ao;
    cudaGetSymbolAddress((void**)&xh,  g_xh);
    cudaGetSymbolAddress((void**)&Wqt, g_Wqt);
    cudaGetSymbolAddress((void**)&Wpt, g_Wpt);
    cudaGetSymbolAddress((void**)&Qh,  g_Qh);
    cudaGetSymbolAddress((void**)&xph, g_xph);
    cudaGetSymbolAddress((void**)&KVh, g_KVh);
    cudaGetSymbolAddress((void**)&kfh, g_kfh);
    cudaGetSymbolAddress((void**)&vth, g_vth);
    cudaGetSymbolAddress((void**)&ao,  g_ao);

    cudaFuncSetAttribute(attn_tc,
                         cudaFuncAttributeMaxDynamicSharedMemorySize, ATTN_SMEM);

    // 0) conversions + weight transposes
    f2h_kernel<<<(B_*N_*C_/4 + 255)/256, 256>>>(x, xh, B_*N_*C_/4);
    f2h_T<<<dim3(3*C_/32, C_/32), dim3(32, 8)>>>(Wqkv, Wqt, C_, 3*C_);
    f2h_T<<<dim3(C_/32, C_/32), dim3(32, 8)>>>(Wproj, Wpt, C_, C_);

    // 1) pooled tokens -> fp16
    pool_kernel<<<(B_*L_*C_/4 + 255)/256, 256>>>(x, xph);

    // 2) Q = x @ Wqkv[:,0:768] + bqkv  -> fp16
    hgemm<<<dim3(C_/128, B_*N_/128), 256>>>(xh, Wqt, bqkv, Qh,
                                            C_, C_, C_, C_, 1);

    // 3) KV = xp @ Wqkv[:,768:2304] + bqkv[768:] -> fp16
    hgemm<<<dim3(2*C_/128, B_*L_/128), 256>>>(xph, Wqt + (long)C_*C_,
                                              bqkv + C_, KVh,
                                              C_, C_, C_, 2*C_, 1);

    // 4) tensor-core compress + bank concat (K: [k][d], V: [d][k])
    kvcompress<<<dim3(2, H_, B_), 128>>>(KVh, E_k, E_v, k_bank, v_bank,
                                         kfh, vth);

    // 5) fp16 tensor-core attention
    attn_tc<<<dim3(N_/128, H_, B_), 256, ATTN_SMEM>>>(Qh, kfh, vth, ao);

    // 6) out = ao @ Wproj + bproj -> fp32
    hgemm<<<dim3(C_/128, B_*N_/128), 256>>>(ao, Wpt, bproj, (float*)d_out,
                                            C_, C_, C_, C_, 0);
}

// round 8
// speedup vs baseline: 2.0801x; 1.1148x over previous
#include <cuda_runtime.h>
#include <cuda_fp16.h>
#include <math.h>
#include <stdint.h>

#define B_  32
#define N_  1024
#define C_  768
#define H_  12
#define D_  64
#define L_  128

// ---------------- scratch (device globals: no allocations allowed) ----------
__device__ __half g_xh [B_*N_*C_];      // x in fp16
__device__ __half g_Wqt[3*C_*C_];       // Wqkv^T  [2304][768] fp16
__device__ __half g_Wpt[C_*C_];         // Wproj^T [768][768] fp16
__device__ __half g_Qh [B_*N_*C_];      // Q projection, fp16
__device__ __half g_xph[B_*L_*C_];      // pooled tokens, fp16
__device__ __half g_KVh[B_*L_*2*C_];    // K|V projections, fp16
__device__ __half g_kfh[B_*H_*L_*D_];   // k_full fp16 [bh][128][64]
__device__ __half g_vth[B_*H_*D_*L_];   // v_full fp16 TRANSPOSED [bh][64][128]
__device__ __half g_ao [B_*N_*C_];      // attention output, fp16

__device__ __forceinline__ void mma_f16(
    float* c, uint32_t a0, uint32_t a1, uint32_t a2, uint32_t a3,
    uint32_t b0, uint32_t b1)
{
    asm volatile(
        "mma.sync.aligned.m16n8k16.row.col.f32.f16.f16.f32 "
        "{%0,%1,%2,%3}, {%4,%5,%6,%7}, {%8,%9}, {%0,%1,%2,%3};"
        : "+f"(c[0]), "+f"(c[1]), "+f"(c[2]), "+f"(c[3])
        : "r"(a0), "r"(a1), "r"(a2), "r"(a3), "r"(b0), "r"(b1));
}

__device__ __forceinline__ void ldsm4(uint32_t& r0, uint32_t& r1,
                                      uint32_t& r2, uint32_t& r3, uint32_t addr)
{
    asm volatile("ldmatrix.sync.aligned.m8n8.x4.shared.b16 {%0,%1,%2,%3}, [%4];"
                 : "=r"(r0), "=r"(r1), "=r"(r2), "=r"(r3) : "r"(addr));
}

__device__ __forceinline__ void cp16(uint32_t saddr, const void* g) {
    asm volatile("cp.async.ca.shared.global [%0], [%1], 16;"
                 :: "r"(saddr), "l"(g));
}

// ---------------- fp32 -> fp16 converter ------------------------------------
__global__ void f2h_kernel(const float* __restrict__ s, __half* __restrict__ d,
                           int n4)
{
    int i = blockIdx.x * blockDim.x + threadIdx.x;
    if (i >= n4) return;
    float4 v = *reinterpret_cast<const float4*>(s + (long)i*4);
    __half2 h0 = __float22half2_rn(make_float2(v.x, v.y));
    __half2 h1 = __float22half2_rn(make_float2(v.z, v.w));
    uint2 o;
    o.x = *reinterpret_cast<uint32_t*>(&h0);
    o.y = *reinterpret_cast<uint32_t*>(&h1);
    *reinterpret_cast<uint2*>(d + (long)i*4) = o;
}

// ---------------- fp32 -> fp16 transpose: Wt[c][r] = W[r][c] ----------------
__global__ void f2h_T(const float* __restrict__ W, __half* __restrict__ Wt,
                      int rows, int cols)
{
    __shared__ float s[32][33];
    int c0 = blockIdx.x*32, r0 = blockIdx.y*32;
    int tx = threadIdx.x, ty = threadIdx.y;   // 32 x 8
    #pragma unroll
    for (int i = 0; i < 32; i += 8)
        s[ty+i][tx] = W[(long)(r0+ty+i)*cols + c0+tx];
    __syncthreads();
    #pragma unroll
    for (int i = 0; i < 32; i += 8)
        Wt[(long)(c0+ty+i)*rows + r0+tx] = __float2half_rn(s[tx][ty+i]);
}

// ---------------- pooling -> fp16: xp[b,p,c] = .5*(x[2p]+x[2p+1]) -----------
__global__ void pool_kernel(const float* __restrict__ x, __half* __restrict__ xp)
{
    int i = blockIdx.x * blockDim.x + threadIdx.x;      // 4-elem index
    const int TOT4 = B_*L_*C_/4;
    if (i >= TOT4) return;
    int c4 = i % (C_/4);
    int p  = (i / (C_/4)) % L_;
    int b  = i / (C_/4 * L_);
    long base = (long)b*N_*C_ + (long)(2*p)*C_ + c4*4;
    float4 a = *reinterpret_cast<const float4*>(x + base);
    float4 c = *reinterpret_cast<const float4*>(x + base + C_);
    __half2 h0 = __float22half2_rn(make_float2(0.5f*(a.x+c.x), 0.5f*(a.y+c.y)));
    __half2 h1 = __float22half2_rn(make_float2(0.5f*(a.z+c.z), 0.5f*(a.w+c.w)));
    uint2 o;
    o.x = *reinterpret_cast<uint32_t*>(&h0);
    o.y = *reinterpret_cast<uint32_t*>(&h1);
    *reinterpret_cast<uint2*>(xp + (long)i*4) = o;
}

// -------- fp16 GEMM, cp.async double-buffered, ldmatrix fragments -----------
// A [M,K] fp16 row-major; Bt [N,K] fp16 row-major (pre-transposed weights).
// 128x128 tile, BK=32, 256 threads, warp tile 64x32, 2 CTAs/SM.
#define TH_STR 40      // halves per smem row (32 data + 8 pad); 20 words

__global__ __launch_bounds__(256, 2) void hgemm(
    const __half* __restrict__ A, const __half* __restrict__ Bt,
    const float* __restrict__ bias, void* __restrict__ Cv,
    int K, int lda, int ldbt, int ldc, int half_out)
{
    __shared__ __half Ah[2][128*TH_STR];
    __shared__ __half Bh[2][128*TH_STR];

    const int t    = threadIdx.x;
    const int warp = t >> 5;
    const int lane = t & 31;
    const int group = lane >> 2;
    const int tid4  = lane & 3;
    const int wm = (warp & 1) * 64;
    const int wn = (warp >> 1) * 32;

    const int bm = blockIdx.y * 128, bn = blockIdx.x * 128;

    float acc[4][4][4];
    #pragma unroll
    for (int mf = 0; mf < 4; mf++)
        #pragma unroll
        for (int nf = 0; nf < 4; nf++)
            #pragma unroll
            for (int r = 0; r < 4; r++) acc[mf][nf][r] = 0.f;

    const uint32_t aB0 = (uint32_t)__cvta_generic_to_shared(&Ah[0][0]);
    const uint32_t aB1 = (uint32_t)__cvta_generic_to_shared(&Ah[1][0]);
    const uint32_t bB0 = (uint32_t)__cvta_generic_to_shared(&Bh[0][0]);
    const uint32_t bB1 = (uint32_t)__cvta_generic_to_shared(&Bh[1][0]);

    // ldmatrix per-lane offsets (bytes, relative to buffer base)
    const int lane15 = lane & 15;
    const int lanehi = lane >> 4;           // 0/1 -> k-word +0/+4
    uint32_t aOff[4];
    #pragma unroll
    for (int mf = 0; mf < 4; mf++)
        aOff[mf] = ((wm + mf*16 + lane15)*20 + lanehi*4)*4;
    const int bsel = lane >> 3;             // 0..3
    uint32_t bOff[2];
    #pragma unroll
    for (int pr = 0; pr < 2; pr++) {
        int row = wn + (pr*2 + (bsel>>1))*8 + (lane & 7);
        bOff[pr] = (row*20 + (bsel & 1)*4)*4;
    }

    // copy assignments
    const int ar0 = t >> 2,        aof = (t & 3) * 8;
    const int ar1 = ar0 + 64;
    const int br  = t >> 1,        bof = (t & 1) * 16;

    const int ns = K >> 5;

    // prologue
    cp16(aB0 + (ar0*TH_STR + aof)*2, A + (long)(bm + ar0)*lda + aof);
    cp16(aB0 + (ar1*TH_STR + aof)*2, A + (long)(bm + ar1)*lda + aof);
    cp16(bB0 + (br*TH_STR + bof)*2,     Bt + (long)(bn + br)*ldbt + bof);
    cp16(bB0 + (br*TH_STR + bof + 8)*2, Bt + (long)(bn + br)*ldbt + bof + 8);
    asm volatile("cp.async.commit_group;");

    for (int i = 0; i < ns; i++) {
        const int buf = i & 1;
        asm volatile("cp.async.wait_all;" ::: "memory");
        __syncthreads();

        if (i + 1 < ns) {
            const int kn = (i + 1) << 5;
            const uint32_t aB = buf ? aB0 : aB1;
            const uint32_t bB = buf ? bB0 : bB1;
            cp16(aB + (ar0*TH_STR + aof)*2, A + (long)(bm + ar0)*lda + kn + aof);
            cp16(aB + (ar1*TH_STR + aof)*2, A + (long)(bm + ar1)*lda + kn + aof);
            cp16(bB + (br*TH_STR + bof)*2,     Bt + (long)(bn + br)*ldbt + kn + bof);
            cp16(bB + (br*TH_STR + bof + 8)*2, Bt + (long)(bn + br)*ldbt + kn + bof + 8);
            asm volatile("cp.async.commit_group;");
        }

        const uint32_t aB = buf ? aB1 : aB0;
        const uint32_t bB = buf ? bB1 : bB0;

        #pragma unroll
        for (int ks = 0; ks < 2; ks++) {
            const uint32_t kwB = ks * 8 * 4;     // k-word offset in bytes
            uint32_t a[4][4], b[4][2];
            #pragma unroll
            for (int mf = 0; mf < 4; mf++)
                ldsm4(a[mf][0], a[mf][1], a[mf][2], a[mf][3],
                      aB + aOff[mf] + kwB);
            ldsm4(b[0][0], b[0][1], b[1][0], b[1][1], bB + bOff[0] + kwB);
            ldsm4(b[2][0], b[2][1], b[3][0], b[3][1], bB + bOff[1] + kwB);
            #pragma unroll
            for (int mf = 0; mf < 4; mf++)
                #pragma unroll
                for (int nf = 0; nf < 4; nf++)
                    mma_f16(acc[mf][nf], a[mf][0], a[mf][1], a[mf][2], a[mf][3],
                            b[nf][0], b[nf][1]);
        }
        __syncthreads();
    }

    if (half_out) {
        __half* C = reinterpret_cast<__half*>(Cv);
        #pragma unroll
        for (int mf = 0; mf < 4; mf++) {
            long r0 = bm + wm + mf*16 + group;
            #pragma unroll
            for (int nf = 0; nf < 4; nf++) {
                int c0 = bn + wn + nf*8 + tid4*2;
                float2 bi = *reinterpret_cast<const float2*>(bias + c0);
                __half2 h0 = __float22half2_rn(
                    make_float2(acc[mf][nf][0] + bi.x, acc[mf][nf][1] + bi.y));
                __half2 h1 = __float22half2_rn(
                    make_float2(acc[mf][nf][2] + bi.x, acc[mf][nf][3] + bi.y));
                *reinterpret_cast<__half2*>(C + r0*ldc + c0) = h0;
                *reinterpret_cast<__half2*>(C + (r0+8)*ldc + c0) = h1;
            }
        }
    } else {
        float* C = reinterpret_cast<float*>(Cv);
        #pragma unroll
        for (int mf = 0; mf < 4; mf++) {
            long r0 = bm + wm + mf*16 + group;
            #pragma unroll
            for (int nf = 0; nf < 4; nf++) {
                int c0 = bn + wn + nf*8 + tid4*2;
                float2 bi = *reinterpret_cast<const float2*>(bias + c0);
                float2 o0, o1;
                o0.x = acc[mf][nf][0] + bi.x; o0.y = acc[mf][nf][1] + bi.y;
                o1.x = acc[mf][nf][2] + bi.x; o1.y = acc[mf][nf][3] + bi.y;
                *reinterpret_cast<float2*>(C + r0*ldc + c0) = o0;
                *reinterpret_cast<float2*>(C + (r0+8)*ldc + c0) = o1;
            }
        }
    }
}

// ------ tensor-core kvcompress: out = E^T @ KV_head (64x64x128), + bank -----
__global__ __launch_bounds__(128) void kvcompress(
    const __half* __restrict__ KV, const float* __restrict__ E_k,
    const float* __restrict__ E_v, const float* __restrict__ k_bank,
    const float* __restrict__ v_bank, __half* __restrict__ kf,
    __half* __restrict__ vt)
{
    __shared__ __half Et[64*136];   // [c][s], stride 136 halves (68 words)
    __shared__ __half Kt[64*136];   // [d][s]

    const int which = blockIdx.x, h = blockIdx.y, b = blockIdx.z;
    const float* E    = which ? E_v : E_k;
    const float* bank = which ? v_bank : k_bank;

    const int t = threadIdx.x;
    const int warp = t >> 5, lane = t & 31;
    const int group = lane >> 2, tid4 = lane & 3;

    for (int i = t*4; i < 128*64; i += 512) {
        int s = i >> 6, c = i & 63;
        float4 v = *reinterpret_cast<const float4*>(E + s*64 + c);
        Et[(c+0)*136 + s] = __float2half_rn(v.x);
        Et[(c+1)*136 + s] = __float2half_rn(v.y);
        Et[(c+2)*136 + s] = __float2half_rn(v.z);
        Et[(c+3)*136 + s] = __float2half_rn(v.w);
    }
    const __half* kvp = KV + (long)b*L_*2*C_ + which*C_ + h*D_;
    for (int i = t*4; i < 128*64; i += 512) {
        int s = i >> 6, d = i & 63;
        uint2 raw = *reinterpret_cast<const uint2*>(kvp + (long)s*2*C_ + d);
        const __half* hp = reinterpret_cast<const __half*>(&raw);
        Kt[(d+0)*136 + s] = hp[0];
        Kt[(d+1)*136 + s] = hp[1];
        Kt[(d+2)*136 + s] = hp[2];
        Kt[(d+3)*136 + s] = hp[3];
    }
    __syncthreads();

    float acc[8][4];
    #pragma unroll
    for (int nf = 0; nf < 8; nf++)
        #pragma unroll
        for (int r = 0; r < 4; r++) acc[nf][r] = 0.f;

    const uint32_t* Ew = reinterpret_cast<const uint32_t*>(Et);
    const uint32_t* Kw = reinterpret_cast<const uint32_t*>(Kt);
    const int m0 = warp*16 + group;

    #pragma unroll
    for (int ks = 0; ks < 8; ks++) {
        const int kw = ks * 8;
        uint32_t a0 = Ew[(m0    )*68 + kw + tid4];
        uint32_t a1 = Ew[(m0 + 8)*68 + kw + tid4];
        uint32_t a2 = Ew[(m0    )*68 + kw + tid4 + 4];
        uint32_t a3 = Ew[(m0 + 8)*68 + kw + tid4 + 4];
        #pragma unroll
        for (int nf = 0; nf < 8; nf++) {
            uint32_t b0 = Kw[(nf*8+group)*68 + kw + tid4];
            uint32_t b1 = Kw[(nf*8+group)*68 + kw + tid4 + 4];
            mma_f16(acc[nf], a0, a1, a2, a3, b0, b1);
        }
    }

    const long bh = (long)(b*H_ + h);
    if (which == 0) {
        __half* out = kf + bh*L_*D_;            // [128][64]
        #pragma unroll
        for (int nf = 0; nf < 8; nf++) {
            int d = nf*8 + tid4*2;
            __half2 h0 = __float22half2_rn(make_float2(acc[nf][0], acc[nf][1]));
            __half2 h1 = __float22half2_rn(make_float2(acc[nf][2], acc[nf][3]));
            *reinterpret_cast<__half2*>(out + (m0  )*64 + d) = h0;
            *reinterpret_cast<__half2*>(out + (m0+8)*64 + d) = h1;
        }
        __syncthreads();
        for (int i = t*4; i < 64*64; i += 512) {
            int r = i >> 6, d = i & 63;
            float4 v = *reinterpret_cast<const float4*>(
                bank + (long)b*64*C_ + (long)r*C_ + h*D_ + d);
            __half2 h0 = __float22half2_rn(make_float2(v.x, v.y));
            __half2 h1 = __float22half2_rn(make_float2(v.z, v.w));
            *reinterpret_cast<__half2*>(out + (64+r)*64 + d) = h0;
            *reinterpret_cast<__half2*>(out + (64+r)*64 + d + 2) = h1;
        }
    } else {
        __half* out = vt + bh*D_*L_;            // [64][128] (d-major)
        #pragma unroll
        for (int nf = 0; nf < 8; nf++) {
            int d = nf*8 + tid4*2;
            out[(d  )*128 + m0    ] = __float2half_rn(acc[nf][0]);
            out[(d+1)*128 + m0    ] = __float2half_rn(acc[nf][1]);
            out[(d  )*128 + m0 + 8] = __float2half_rn(acc[nf][2]);
            out[(d+1)*128 + m0 + 8] = __float2half_rn(acc[nf][3]);
        }
        __syncthreads();
        for (int i = t*4; i < 64*64; i += 512) {
            int r = i >> 6, d = i & 63;
            float4 v = *reinterpret_cast<const float4*>(
                bank + (long)b*64*C_ + (long)r*C_ + h*D_ + d);
            out[(d  )*128 + 64 + r] = __float2half_rn(v.x);
            out[(d+1)*128 + 64 + r] = __float2half_rn(v.y);
            out[(d+2)*128 + 64 + r] = __float2half_rn(v.z);
            out[(d+3)*128 + 64 + r] = __float2half_rn(v.w);
        }
    }
}

// -------- fp16 tensor-core attention, ldmatrix fragments --------------------
#define QS_W 36
#define VS_W 68
#define ATTN_SMEM ((128*QS_W + 64*VS_W + 128*VS_W + 128*QS_W) * 4)

__global__ __launch_bounds__(256, 2) void attn_tc(
    const __half* __restrict__ Q, const __half* __restrict__ kf,
    const __half* __restrict__ vt, __half* __restrict__ O)
{
    extern __shared__ uint32_t smu[];
    uint32_t* Ksw = smu;                      // [128][36]
    uint32_t* Vtw = Ksw + 128*QS_W;           // [64][68]
    uint32_t* Psw = Vtw + 64*VS_W;            // [128][68]
    uint32_t* Qsw = Psw + 128*VS_W;           // [128][36]

    const int t = threadIdx.x;
    const int warp = t >> 5, lane = t & 31;
    const int group = lane >> 2, tid4 = lane & 3;
    const int qb = blockIdx.x, h = blockIdx.y, b = blockIdx.z;

    const __half* kfp = kf + (long)(b*H_ + h) * L_ * D_;   // [128][64]
    const __half* vtp = vt + (long)(b*H_ + h) * D_ * L_;   // [64][128]

    for (int i = t*8; i < L_*D_; i += 2048) {
        int k = i >> 6, d = i & 63;
        *reinterpret_cast<uint4*>(&Ksw[k*QS_W + (d>>1)]) =
            *reinterpret_cast<const uint4*>(kfp + i);
    }
    for (int i = t*8; i < D_*L_; i += 2048) {
        int d = i >> 7, k = i & 127;
        *reinterpret_cast<uint4*>(&Vtw[d*VS_W + (k>>1)]) =
            *reinterpret_cast<const uint4*>(vtp + i);
    }
    {
        long base = ((long)b*N_ + qb*128) * C_ + h*D_;
        for (int i = t*8; i < 128*64; i += 2048) {
            int q = i >> 6, d = i & 63;
            *reinterpret_cast<uint4*>(&Qsw[q*QS_W + (d>>1)]) =
                *reinterpret_cast<const uint4*>(Q + base + (long)q*C_ + d);
        }
    }
    __syncthreads();

    const uint32_t kBase = (uint32_t)__cvta_generic_to_shared(Ksw);
    const uint32_t vBase = (uint32_t)__cvta_generic_to_shared(Vtw);
    const uint32_t pBase = (uint32_t)__cvta_generic_to_shared(Psw);
    const uint32_t qBase = (uint32_t)__cvta_generic_to_shared(Qsw);

    const int lane15 = lane & 15;
    const int lanehi = lane >> 4;
    const int bsel = lane >> 3;
    const int qrow = warp*16;

    // --- S = Q K^T ---
    float accS[16][4];
    #pragma unroll
    for (int nt = 0; nt < 16; nt++)
        #pragma unroll
        for (int r = 0; r < 4; r++) accS[nt][r] = 0.f;

    const uint32_t qOff = ((qrow + lane15)*QS_W + lanehi*4)*4;
    uint32_t kOff[8];
    #pragma unroll
    for (int pr = 0; pr < 8; pr++) {
        int krow = pr*16 + (bsel>>1)*8 + (lane & 7);
        kOff[pr] = (krow*QS_W + (bsel & 1)*4)*4;
    }

    #pragma unroll
    for (int ks = 0; ks < 4; ks++) {
        const uint32_t kwB = ks * 32;       // 8 words * 4B
        uint32_t a0, a1, a2, a3;
        ldsm4(a0, a1, a2, a3, qBase + qOff + kwB);
        #pragma unroll
        for (int pr = 0; pr < 8; pr++) {
            uint32_t b00, b01, b10, b11;
            ldsm4(b00, b01, b10, b11, kBase + kOff[pr] + kwB);
            mma_f16(accS[pr*2  ], a0, a1, a2, a3, b00, b01);
            mma_f16(accS[pr*2+1], a0, a1, a2, a3, b10, b11);
        }
    }

    // --- softmax over 128 keys ---
    const float scale = 0.125f;
    float m0 = -1e30f, m1 = -1e30f;
    #pragma unroll
    for (int nt = 0; nt < 16; nt++) {
        accS[nt][0] *= scale; accS[nt][1] *= scale;
        accS[nt][2] *= scale; accS[nt][3] *= scale;
        m0 = fmaxf(m0, fmaxf(accS[nt][0], accS[nt][1]));
        m1 = fmaxf(m1, fmaxf(accS[nt][2], accS[nt][3]));
    }
    m0 = fmaxf(m0, __shfl_xor_sync(0xffffffff, m0, 1));
    m0 = fmaxf(m0, __shfl_xor_sync(0xffffffff, m0, 2));
    m1 = fmaxf(m1, __shfl_xor_sync(0xffffffff, m1, 1));
    m1 = fmaxf(m1, __shfl_xor_sync(0xffffffff, m1, 2));

    float l0 = 0.f, l1 = 0.f;
    #pragma unroll
    for (int nt = 0; nt < 16; nt++) {
        accS[nt][0] = expf(accS[nt][0] - m0);
        accS[nt][1] = expf(accS[nt][1] - m0);
        accS[nt][2] = expf(accS[nt][2] - m1);
        accS[nt][3] = expf(accS[nt][3] - m1);
        l0 += accS[nt][0] + accS[nt][1];
        l1 += accS[nt][2] + accS[nt][3];
    }
    l0 += __shfl_xor_sync(0xffffffff, l0, 1);
    l0 += __shfl_xor_sync(0xffffffff, l0, 2);
    l1 += __shfl_xor_sync(0xffffffff, l1, 1);
    l1 += __shfl_xor_sync(0xffffffff, l1, 2);
    float rl0 = 1.f / l0, rl1 = 1.f / l1;

    // --- store P (normalized) fp16 ---
    #pragma unroll
    for (int nt = 0; nt < 16; nt++) {
        __half2 p0 = __float22half2_rn(
            make_float2(accS[nt][0]*rl0, accS[nt][1]*rl0));
        __half2 p1 = __float22half2_rn(
            make_float2(accS[nt][2]*rl1, accS[nt][3]*rl1));
        Psw[(qrow+group  )*VS_W + nt*4 + tid4] = *reinterpret_cast<uint32_t*>(&p0);
        Psw[(qrow+group+8)*VS_W + nt*4 + tid4] = *reinterpret_cast<uint32_t*>(&p1);
    }
    __syncwarp();

    // --- O = P V ---
    float accO[8][4];
    #pragma unroll
    for (int nt = 0; nt < 8; nt++)
        #pragma unroll
        for (int r = 0; r < 4; r++) accO[nt][r] = 0.f;

    const uint32_t pOff = ((qrow + lane15)*VS_W + lanehi*4)*4;
    uint32_t vOff[4];
    #pragma unroll
    for (int pr = 0; pr < 4; pr++) {
        int drow = pr*16 + (bsel>>1)*8 + (lane & 7);
        vOff[pr] = (drow*VS_W + (bsel & 1)*4)*4;
    }

    #pragma unroll
    for (int ks = 0; ks < 8; ks++) {
        const uint32_t kwB = ks * 32;
        uint32_t a0, a1, a2, a3;
        ldsm4(a0, a1, a2, a3, pBase + pOff + kwB);
        #pragma unroll
        for (int pr = 0; pr < 4; pr++) {
            uint32_t b00, b01, b10, b11;
            ldsm4(b00, b01, b10, b11, vBase + vOff[pr] + kwB);
            mma_f16(accO[pr*2  ], a0, a1, a2, a3, b00, b01);
            mma_f16(accO[pr*2+1], a0, a1, a2, a3, b10, b11);
        }
    }

    long row0 = (long)b*N_ + qb*128 + qrow + group;
    #pragma unroll
    for (int nt = 0; nt < 8; nt++) {
        int col = h*D_ + nt*8 + tid4*2;
        __half2 h0 = __float22half2_rn(make_float2(accO[nt][0], accO[nt][1]));
        __half2 h1 = __float22half2_rn(make_float2(accO[nt][2], accO[nt][3]));
        *reinterpret_cast<__half2*>(O + row0*C_ + col) = h0;
        *reinterpret_cast<__half2*>(O + (row0+8)*C_ + col) = h1;
    }
}

// ---------------------------------------------------------------------------
extern "C" void kernel_launch(void* const* d_in, const int* in_sizes, int n_in,
                              void* d_out, int out_size)
{
    const float* x      = (const float*)d_in[0];
    const float* Wqkv   = (const float*)d_in[1];
    const float* bqkv   = (const float*)d_in[2];
    const float* E_k    = (const float*)d_in[3];
    const float* E_v    = (const float*)d_in[4];
    const float* Wproj  = (const float*)d_in[5];
    const float* bproj  = (const float*)d_in[6];
    const float* k_bank = (const float*)d_in[7];
    const float* v_bank = (const float*)d_in[8];

    __half *xh, *Wqt, *Wpt, *Qh, *xph, *KVh, *kfh, *vth, *ao;
    cudaGetSymbolAddress((void**)&xh,  g_xh);
    cudaGetSymbolAddress((void**)&Wqt, g_Wqt);
    cudaGetSymbolAddress((void**)&Wpt, g_Wpt);
    cudaGetSymbolAddress((void**)&Qh,  g_Qh);
    cudaGetSymbolAddress((void**)&xph, g_xph);
    cudaGetSymbolAddress((void**)&KVh, g_KVh);
    cudaGetSymbolAddress((void**)&kfh, g_kfh);
    cudaGetSymbolAddress((void**)&vth, g_vth);
    cudaGetSymbolAddress((void**)&ao,  g_ao);

    cudaFuncSetAttribute(attn_tc,
                         cudaFuncAttributeMaxDynamicSharedMemorySize, ATTN_SMEM);

    // 0) conversions + weight transposes
    f2h_kernel<<<(B_*N_*C_/4 + 255)/256, 256>>>(x, xh, B_*N_*C_/4);
    f2h_T<<<dim3(3*C_/32, C_/32), dim3(32, 8)>>>(Wqkv, Wqt, C_, 3*C_);
    f2h_T<<<dim3(C_/32, C_/32), dim3(32, 8)>>>(Wproj, Wpt, C_, C_);

    // 1) pooled tokens -> fp16
    pool_kernel<<<(B_*L_*C_/4 + 255)/256, 256>>>(x, xph);

    // 2) Q = x @ Wqkv[:,0:768] + bqkv  -> fp16
    hgemm<<<dim3(C_/128, B_*N_/128), 256>>>(xh, Wqt, bqkv, Qh,
                                            C_, C_, C_, C_, 1);

    // 3) KV = xp @ Wqkv[:,768:2304] + bqkv[768:] -> fp16
    hgemm<<<dim3(2*C_/128, B_*L_/128), 256>>>(xph, Wqt + (long)C_*C_,
                                              bqkv + C_, KVh,
                                              C_, C_, C_, 2*C_, 1);

    // 4) tensor-core compress + bank concat (K: [k][d], V: [d][k])
    kvcompress<<<dim3(2, H_, B_), 128>>>(KVh, E_k, E_v, k_bank, v_bank,
                                         kfh, vth);

    // 5) fp16 tensor-core attention
    attn_tc<<<dim3(N_/128, H_, B_), 256, ATTN_SMEM>>>(Qh, kfh, vth, ao);

    // 6) out = ao @ Wproj + bproj -> fp32
    hgemm<<<dim3(C_/128, B_*N_/128), 256>>>(ao, Wpt, bproj, (float*)d_out,
                                            C_, C_, C_, C_, 0);
}